// round 14
// baseline (speedup 1.0000x reference)
#include <cuda_runtime.h>
#include <cuda_bf16.h>
#include <cstdint>

// Problem constants
#define SS 1024
#define BB 4
#define HH 16
#define DD 64
#define EE 1024
#define BHH 64   // B*H

// ---------------------------------------------------------------------------
// Scratch (device globals)
// ---------------------------------------------------------------------------
__device__ __nv_bfloat16 g_qhi[BHH * SS * DD], g_qlo[BHH * SS * DD];
__device__ __nv_bfloat16 g_khi[BHH * SS * DD], g_klo[BHH * SS * DD];
__device__ __nv_bfloat16 g_vhi[BHH * SS * DD], g_vlo[BHH * SS * DD];

__device__ __nv_bfloat16 g_xhi[4096 * 1024], g_xlo[4096 * 1024];
__device__ __nv_bfloat16 g_wihi[3072 * 1024], g_wilo[3072 * 1024];
__device__ __nv_bfloat16 g_wohi[1024 * 1024], g_wolo[1024 * 1024];
__device__ __nv_bfloat16 g_ahi[4096 * 1024], g_alo[4096 * 1024];

// ---------------------------------------------------------------------------
// Warp-level MMA helpers (baseline PTX, works on sm_103 non-'a' target)
// ---------------------------------------------------------------------------
__device__ __forceinline__ uint32_t smem_u32(const void* p) {
    uint32_t a;
    asm("{ .reg .u64 t; cvta.to.shared.u64 t, %1; cvt.u32.u64 %0, t; }"
        : "=r"(a) : "l"(p));
    return a;
}

__device__ __forceinline__ void ldm_x4(uint32_t* r, uint32_t addr) {
    asm volatile("ldmatrix.sync.aligned.m8n8.x4.shared.b16 {%0,%1,%2,%3}, [%4];"
                 : "=r"(r[0]), "=r"(r[1]), "=r"(r[2]), "=r"(r[3]) : "r"(addr));
}
__device__ __forceinline__ void ldm_x2(uint32_t* r, uint32_t addr) {
    asm volatile("ldmatrix.sync.aligned.m8n8.x2.shared.b16 {%0,%1}, [%2];"
                 : "=r"(r[0]), "=r"(r[1]) : "r"(addr));
}
__device__ __forceinline__ void ldm_x2t(uint32_t* r, uint32_t addr) {
    asm volatile("ldmatrix.sync.aligned.m8n8.x2.trans.shared.b16 {%0,%1}, [%2];"
                 : "=r"(r[0]), "=r"(r[1]) : "r"(addr));
}

// D(f32) += A(bf16) @ B(bf16), m16n8k16
__device__ __forceinline__ void mma_bf16(float* c, const uint32_t* a, const uint32_t* b) {
    asm volatile(
        "mma.sync.aligned.m16n8k16.row.col.f32.bf16.bf16.f32 "
        "{%0,%1,%2,%3}, {%4,%5,%6,%7}, {%8,%9}, {%0,%1,%2,%3};"
        : "+f"(c[0]), "+f"(c[1]), "+f"(c[2]), "+f"(c[3])
        : "r"(a[0]), "r"(a[1]), "r"(a[2]), "r"(a[3]), "r"(b[0]), "r"(b[1]));
}

// cp.async 16B
__device__ __forceinline__ void cp16(uint32_t dst, const void* src) {
    asm volatile("cp.async.cg.shared.global [%0], [%1], 16;" :: "r"(dst), "l"(src));
}
#define CP_COMMIT() asm volatile("cp.async.commit_group;" ::: "memory")
#define CP_WAIT(N)  asm volatile("cp.async.wait_group %0;" :: "n"(N) : "memory")

// pack two fp32 -> bf16x2 (x0 in low half, x1 in high half)
__device__ __forceinline__ uint32_t pack2(float x0, float x1) {
    uint32_t r;
    asm("cvt.rn.bf16x2.f32 %0, %1, %2;" : "=r"(r) : "f"(x1), "f"(x0));
    return r;
}
// split pair into hi/lo bf16x2
__device__ __forceinline__ void split2(float x0, float x1, uint32_t& hi, uint32_t& lo) {
    uint32_t hv = pack2(x0, x1);
    float h0 = __uint_as_float(hv << 16);
    float h1 = __uint_as_float(hv & 0xFFFF0000u);
    hi = hv;
    lo = pack2(x0 - h0, x1 - h1);
}

// ---------------------------------------------------------------------------
// fp32 -> bf16 hi/lo splits for x, W_in, W_out in ONE launch.
// blocks [0,4096): x | [4096,7168): W_in | [7168,8192): W_out
// ---------------------------------------------------------------------------
__global__ __launch_bounds__(256) void split_all(const float* __restrict__ x,
                                                 const float* __restrict__ wi,
                                                 const float* __restrict__ wo) {
    int bid = blockIdx.x;
    const float* src;
    __nv_bfloat16 *hi, *lo;
    int i;
    if (bid < 4096)      { src = x;  hi = g_xhi;  lo = g_xlo;  i = bid * 256 + threadIdx.x; }
    else if (bid < 7168) { src = wi; hi = g_wihi; lo = g_wilo; i = (bid - 4096) * 256 + threadIdx.x; }
    else                 { src = wo; hi = g_wohi; lo = g_wolo; i = (bid - 7168) * 256 + threadIdx.x; }

    float4 v = ((const float4*)src)[i];
    uint32_t h0, l0, h1, l1;
    split2(v.x, v.y, h0, l0);
    split2(v.z, v.w, h1, l1);
    ((uint2*)hi)[i] = make_uint2(h0, h1);
    ((uint2*)lo)[i] = make_uint2(l0, l1);
}

// ---------------------------------------------------------------------------
// mma.sync split-bf16 GEMM, cp.async double-buffered, TERM-MAJOR MMA order
// (3 passes of 16 independent MMAs -> no accumulator RAW chains).
// MODE 0: A=x(split), W=W_in(split) -> scatter bf16 hi/lo q/k/v (q*0.125)
// MODE 1: A=attn(split), W=W_out(split) -> write d_out (fp32)
// ---------------------------------------------------------------------------
#define BUF_U4 2560          // uint4 per buffer (4 arrays x 640)
#define ARR_U4 640

template <int MODE>
__global__ __launch_bounds__(256) void gemm_mma(
    const float* __restrict__ bias, float* __restrict__ Cout)
{
    extern __shared__ __align__(16) uint4 smem[];

    const __nv_bfloat16* Ahi = (MODE == 0) ? g_xhi  : g_ahi;
    const __nv_bfloat16* Alo = (MODE == 0) ? g_xlo  : g_alo;
    const __nv_bfloat16* Bhi = (MODE == 0) ? g_wihi : g_wohi;
    const __nv_bfloat16* Blo = (MODE == 0) ? g_wilo : g_wolo;

    const int tid = threadIdx.x;
    const int lane = tid & 31;
    const int wid = tid >> 5;
    const int wm = wid >> 2;
    const int wn = wid & 3;
    const int bm = blockIdx.y, bn = blockIdx.x;
    const int K = 1024;

    float acc[4][4][4];
#pragma unroll
    for (int mf = 0; mf < 4; mf++)
#pragma unroll
        for (int nf = 0; nf < 4; nf++)
#pragma unroll
            for (int e = 0; e < 4; e++) acc[mf][nf][e] = 0.f;

    const uint32_t uS = smem_u32(smem);
    const __nv_bfloat16* gsrc[4] = {Ahi, Alo, Bhi, Blo};

    auto issue = [&](int kt, int b) {
        const int k0 = kt * 32;
#pragma unroll
        for (int q = 0; q < 8; q++) {
            int a = q >> 1;
            int sub = (q & 1) * 256 + tid;
            int row = sub >> 2, kc = sub & 3;
            int gr = (a < 2 ? bm : bn) * 128 + row;
            const __nv_bfloat16* src = gsrc[a] + (size_t)gr * K + k0 + kc * 8;
            uint32_t dst = uS + (uint32_t)(b * BUF_U4 + a * ARR_U4 + row * 5 + kc) * 16u;
            cp16(dst, src);
        }
        CP_COMMIT();
    };

    const int a_row = wm * 64 + (lane & 7) + ((lane >> 3) & 1) * 8;
    const int a_kc  = (lane >> 4) & 1;
    const int b_row = wn * 32 + (lane & 7);
    const int b_kc  = (lane >> 3) & 1;

    issue(0, 0);

    for (int kt = 0; kt < 32; kt++) {
        const int b = kt & 1;
        if (kt < 31) issue(kt + 1, b ^ 1);
        if (kt < 31) { CP_WAIT(1); } else { CP_WAIT(0); }
        __syncthreads();

        const uint32_t uAhi = uS + (uint32_t)(b * BUF_U4) * 16u;
        const uint32_t uAlo = uAhi + ARR_U4 * 16u;
        const uint32_t uBhi = uAlo + ARR_U4 * 16u;
        const uint32_t uBlo = uBhi + ARR_U4 * 16u;

#pragma unroll
        for (int ks = 0; ks < 2; ks++) {
            uint32_t ah[4][4], al[4][4], bh[4][2], bl[4][2];
#pragma unroll
            for (int mf = 0; mf < 4; mf++) {
                uint32_t off = (uint32_t)(((a_row + mf * 16) * 5 + ks * 2 + a_kc) * 16);
                ldm_x4(ah[mf], uAhi + off);
                ldm_x4(al[mf], uAlo + off);
            }
#pragma unroll
            for (int nf = 0; nf < 4; nf++) {
                uint32_t off = (uint32_t)(((b_row + nf * 8) * 5 + ks * 2 + b_kc) * 16);
                ldm_x2(bh[nf], uBhi + off);
                ldm_x2(bl[nf], uBlo + off);
            }
            // term-major: 3 passes of 16 independent MMAs
#pragma unroll
            for (int mf = 0; mf < 4; mf++)
#pragma unroll
                for (int nf = 0; nf < 4; nf++)
                    mma_bf16(acc[mf][nf], ah[mf], bh[nf]);
#pragma unroll
            for (int mf = 0; mf < 4; mf++)
#pragma unroll
                for (int nf = 0; nf < 4; nf++)
                    mma_bf16(acc[mf][nf], ah[mf], bl[nf]);
#pragma unroll
            for (int mf = 0; mf < 4; mf++)
#pragma unroll
                for (int nf = 0; nf < 4; nf++)
                    mma_bf16(acc[mf][nf], al[mf], bh[nf]);
        }
        __syncthreads();   // protect buffer b before kt+2 overwrites it
    }

#pragma unroll
    for (int mf = 0; mf < 4; mf++) {
#pragma unroll
        for (int nf = 0; nf < 4; nf++) {
#pragma unroll
            for (int e = 0; e < 4; e++) {
                int m = bm * 128 + wm * 64 + mf * 16 + (lane >> 2) + ((e >> 1) & 1) * 8;
                int n = bn * 128 + wn * 32 + nf * 8 + (lane & 3) * 2 + (e & 1);
                float v = acc[mf][nf][e] + bias[n];
                if (MODE == 0) {
                    int sidx = m >> 2;
                    int bt = m & 3;
                    int h = n / 192;
                    int rr = n - h * 192;
                    int bh2 = bt * HH + h;
                    __nv_bfloat16 *dh, *dl;
                    int dcol;
                    if (rr < 64)       { dh = g_qhi; dl = g_qlo; dcol = rr;       v *= 0.125f; }
                    else if (rr < 128) { dh = g_khi; dl = g_klo; dcol = rr - 64;  }
                    else               { dh = g_vhi; dl = g_vlo; dcol = rr - 128; }
                    size_t idx = ((size_t)bh2 * SS + sidx) * DD + dcol;
                    __nv_bfloat16 hv = __float2bfloat16(v);
                    __nv_bfloat16 lv = __float2bfloat16(v - __bfloat162float(hv));
                    dh[idx] = hv;
                    dl[idx] = lv;
                } else {
                    Cout[(size_t)m * 1024 + n] = v;
                }
            }
        }
    }
}

// ---------------------------------------------------------------------------
// Flash attention on mma.sync, TERM-MAJOR MMA ordering in QK^T and PV.
// ---------------------------------------------------------------------------
#define TSWZ(row, ch) ((((row)) << 7) + ((((ch) ^ ((row) & 7))) << 4))
#define SBP 68

__global__ __launch_bounds__(128) void attn_mma(
    const float* __restrict__ bias_g, const float* __restrict__ mul_g,
    const int* __restrict__ kpm)
{
    extern __shared__ uint8_t sm[];
    float* sB = (float*)(sm + 32768);
    float* sM = (float*)(sm + 50176);

    const int tid = threadIdx.x;
    const int lane = tid & 31;
    const int warp = tid >> 5;
    const int qt = blockIdx.x, bh = blockIdx.y;
    const int b = bh >> 4, h = bh & 15;
    const uint32_t uSm = smem_u32(sm);

    const __nv_bfloat16* qhi = g_qhi + ((size_t)bh * SS + qt * 64) * DD;
    const __nv_bfloat16* qlo = g_qlo + ((size_t)bh * SS + qt * 64) * DD;
    const __nv_bfloat16* khi = g_khi + (size_t)bh * SS * DD;
    const __nv_bfloat16* klo = g_klo + (size_t)bh * SS * DD;
    const __nv_bfloat16* vhi = g_vhi + (size_t)bh * SS * DD;
    const __nv_bfloat16* vlo = g_vlo + (size_t)bh * SS * DD;
    const float* bbase = bias_g + ((size_t)bh * SS + qt * 64) * SS;
    const float* mbase = mul_g + ((size_t)bh * SS + qt * 64) * SS;
    const int* kp = kpm + b * SS;

    // ---- stage Q into smem (at sB region), load A-fragments, then free it
#pragma unroll
    for (int t = 0; t < 4; t++) {
        int idx = tid + t * 128;
        int row = idx >> 3, ch = idx & 7;
        *(uint4*)(sm + 32768 + TSWZ(row, ch)) = *(const uint4*)(qhi + row * 64 + ch * 8);
        *(uint4*)(sm + 40960 + TSWZ(row, ch)) = *(const uint4*)(qlo + row * 64 + ch * 8);
    }
    __syncthreads();

    uint32_t qh[4][4], ql[4][4];
    {
        int arow = warp * 16 + (lane & 7) + ((lane >> 3) & 1) * 8;
        int akc = (lane >> 4) & 1;
#pragma unroll
        for (int ds = 0; ds < 4; ds++) {
            uint32_t off = (uint32_t)TSWZ(arow, ds * 2 + akc);
            ldm_x4(qh[ds], uSm + 32768 + off);
            ldm_x4(ql[ds], uSm + 40960 + off);
        }
    }

    float acc[8][4];
#pragma unroll
    for (int i = 0; i < 8; i++)
#pragma unroll
        for (int e = 0; e < 4; e++) acc[i][e] = 0.f;
    float m0 = 0.f, m1 = 0.f, l0 = 1.f, l1 = 1.f;   // phantom logit 0

    const int r0 = warp * 16 + (lane >> 2);
    const int cc = (lane & 3) * 2;
    const int brow = lane & 7;
    const int bkc = (lane >> 3) & 1;
    const int vrow = (lane & 7) + ((lane >> 3) & 1) * 8;

    for (int kt = 0; kt < 16; kt++) {
        const int k0 = kt * 64;
        __syncthreads();

#pragma unroll
        for (int t = 0; t < 4; t++) {
            int idx = tid + t * 128;
            int row = idx >> 3, ch = idx & 7;
            size_t go = (size_t)(k0 + row) * 64 + ch * 8;
            uint32_t so = TSWZ(row, ch);
            *(uint4*)(sm + so)         = *(const uint4*)(khi + go);
            *(uint4*)(sm + 8192 + so)  = *(const uint4*)(klo + go);
            *(uint4*)(sm + 16384 + so) = *(const uint4*)(vhi + go);
            *(uint4*)(sm + 24576 + so) = *(const uint4*)(vlo + go);
        }
#pragma unroll
        for (int t = 0; t < 8; t++) {
            int idx = tid + t * 128;
            int row = idx >> 4, c4 = idx & 15;
            int col = c4 * 4;
            int4 mk = *(const int4*)(kp + k0 + col);
            float4 bv = *(const float4*)(bbase + (size_t)row * SS + k0 + col);
            float4 mv = *(const float4*)(mbase + (size_t)row * SS + k0 + col);
            if (mk.x) { bv.x = -1e30f; mv.x = 0.f; }
            if (mk.y) { bv.y = -1e30f; mv.y = 0.f; }
            if (mk.z) { bv.z = -1e30f; mv.z = 0.f; }
            if (mk.w) { bv.w = -1e30f; mv.w = 0.f; }
            *(float4*)&sB[row * SBP + col] = bv;
            *(float4*)&sM[row * SBP + col] = mv;
        }
        __syncthreads();

        // ---- S = bias + Q K^T (3-term, term-major per ds)
        float s[8][4];
#pragma unroll
        for (int nf = 0; nf < 8; nf++) {
            float2 t0 = *(float2*)&sB[r0 * SBP + nf * 8 + cc];
            float2 t1 = *(float2*)&sB[(r0 + 8) * SBP + nf * 8 + cc];
            s[nf][0] = t0.x; s[nf][1] = t0.y; s[nf][2] = t1.x; s[nf][3] = t1.y;
        }
#pragma unroll
        for (int ds = 0; ds < 4; ds++) {
            uint32_t kh2[8][2], kl2[8][2];
#pragma unroll
            for (int nf = 0; nf < 8; nf++) {
                uint32_t off = (uint32_t)TSWZ(nf * 8 + brow, ds * 2 + bkc);
                ldm_x2(kh2[nf], uSm + off);
                ldm_x2(kl2[nf], uSm + 8192 + off);
            }
#pragma unroll
            for (int nf = 0; nf < 8; nf++) mma_bf16(s[nf], qh[ds], kh2[nf]);
#pragma unroll
            for (int nf = 0; nf < 8; nf++) mma_bf16(s[nf], qh[ds], kl2[nf]);
#pragma unroll
            for (int nf = 0; nf < 8; nf++) mma_bf16(s[nf], ql[ds], kh2[nf]);
        }

        // ---- online softmax_1
        float tm0 = s[0][0], tm1 = s[0][2];
#pragma unroll
        for (int nf = 0; nf < 8; nf++) {
            tm0 = fmaxf(tm0, fmaxf(s[nf][0], s[nf][1]));
            tm1 = fmaxf(tm1, fmaxf(s[nf][2], s[nf][3]));
        }
        tm0 = fmaxf(tm0, __shfl_xor_sync(0xffffffffu, tm0, 1));
        tm0 = fmaxf(tm0, __shfl_xor_sync(0xffffffffu, tm0, 2));
        tm1 = fmaxf(tm1, __shfl_xor_sync(0xffffffffu, tm1, 1));
        tm1 = fmaxf(tm1, __shfl_xor_sync(0xffffffffu, tm1, 2));
        float mn0 = fmaxf(m0, tm0), mn1 = fmaxf(m1, tm1);
        float sc0 = __expf(m0 - mn0), sc1 = __expf(m1 - mn1);
        m0 = mn0; m1 = mn1;
        float rs0 = 0.f, rs1 = 0.f;
#pragma unroll
        for (int nf = 0; nf < 8; nf++) {
            s[nf][0] = __expf(s[nf][0] - mn0);
            s[nf][1] = __expf(s[nf][1] - mn0);
            s[nf][2] = __expf(s[nf][2] - mn1);
            s[nf][3] = __expf(s[nf][3] - mn1);
            rs0 += s[nf][0] + s[nf][1];
            rs1 += s[nf][2] + s[nf][3];
        }
        rs0 += __shfl_xor_sync(0xffffffffu, rs0, 1);
        rs0 += __shfl_xor_sync(0xffffffffu, rs0, 2);
        rs1 += __shfl_xor_sync(0xffffffffu, rs1, 1);
        rs1 += __shfl_xor_sync(0xffffffffu, rs1, 2);
        l0 = l0 * sc0 + rs0;
        l1 = l1 * sc1 + rs1;
#pragma unroll
        for (int i = 0; i < 8; i++) {
            acc[i][0] *= sc0; acc[i][1] *= sc0;
            acc[i][2] *= sc1; acc[i][3] *= sc1;
        }

        // ---- p *= abm
#pragma unroll
        for (int nf = 0; nf < 8; nf++) {
            float2 t0 = *(float2*)&sM[r0 * SBP + nf * 8 + cc];
            float2 t1 = *(float2*)&sM[(r0 + 8) * SBP + nf * 8 + cc];
            s[nf][0] *= t0.x; s[nf][1] *= t0.y; s[nf][2] *= t1.x; s[nf][3] *= t1.y;
        }

        // ---- acc += P V (3-term, term-major per ks)
#pragma unroll
        for (int ks = 0; ks < 4; ks++) {
            uint32_t ahi[4], alo[4];
            split2(s[2 * ks][0],     s[2 * ks][1],     ahi[0], alo[0]);
            split2(s[2 * ks][2],     s[2 * ks][3],     ahi[1], alo[1]);
            split2(s[2 * ks + 1][0], s[2 * ks + 1][1], ahi[2], alo[2]);
            split2(s[2 * ks + 1][2], s[2 * ks + 1][3], ahi[3], alo[3]);
            uint32_t vh2[8][2], vl2[8][2];
#pragma unroll
            for (int nfd = 0; nfd < 8; nfd++) {
                uint32_t off = (uint32_t)TSWZ(ks * 16 + vrow, nfd);
                ldm_x2t(vh2[nfd], uSm + 16384 + off);
                ldm_x2t(vl2[nfd], uSm + 24576 + off);
            }
#pragma unroll
            for (int nfd = 0; nfd < 8; nfd++) mma_bf16(acc[nfd], ahi, vh2[nfd]);
#pragma unroll
            for (int nfd = 0; nfd < 8; nfd++) mma_bf16(acc[nfd], ahi, vl2[nfd]);
#pragma unroll
            for (int nfd = 0; nfd < 8; nfd++) mma_bf16(acc[nfd], alo, vh2[nfd]);
        }
    }

    // ---- epilogue
    float inv0 = 1.0f / l0, inv1 = 1.0f / l1;
    int q0 = qt * 64 + r0;
    size_t o0 = ((size_t)q0 * BB + b) * EE + h * 64;
    size_t o1 = ((size_t)(q0 + 8) * BB + b) * EE + h * 64;
#pragma unroll
    for (int nfd = 0; nfd < 8; nfd++) {
        int dc = nfd * 8 + cc;
        uint32_t h0, lo0, h1, lo1;
        split2(acc[nfd][0] * inv0, acc[nfd][1] * inv0, h0, lo0);
        split2(acc[nfd][2] * inv1, acc[nfd][3] * inv1, h1, lo1);
        *(uint32_t*)(g_ahi + o0 + dc) = h0;
        *(uint32_t*)(g_alo + o0 + dc) = lo0;
        *(uint32_t*)(g_ahi + o1 + dc) = h1;
        *(uint32_t*)(g_alo + o1 + dc) = lo1;
    }
}

// ---------------------------------------------------------------------------
extern "C" void kernel_launch(void* const* d_in, const int* in_sizes, int n_in,
                              void* d_out, int out_size)
{
    (void)in_sizes; (void)n_in; (void)out_size;
    const float* x         = (const float*)d_in[0];
    const float* attn_bias = (const float*)d_in[1];
    const float* attn_mul  = (const float*)d_in[2];
    const int*   kpm       = (const int*)d_in[3];
    const float* W_in      = (const float*)d_in[4];
    const float* b_in      = (const float*)d_in[5];
    const float* W_out     = (const float*)d_in[6];
    const float* b_out     = (const float*)d_in[7];
    float* out = (float*)d_out;

    const int GEMM_SMEM = 81920;
    const int ATTN_SMEM = 67584;
    cudaFuncSetAttribute(gemm_mma<0>, cudaFuncAttributeMaxDynamicSharedMemorySize, GEMM_SMEM);
    cudaFuncSetAttribute(gemm_mma<1>, cudaFuncAttributeMaxDynamicSharedMemorySize, GEMM_SMEM);
    cudaFuncSetAttribute(attn_mma, cudaFuncAttributeMaxDynamicSharedMemorySize, ATTN_SMEM);

    // fp32 -> bf16 hi/lo splits (single launch)
    split_all<<<8192, 256>>>(x, W_in, W_out);

    // QKV projection
    gemm_mma<0><<<dim3(24, 32), 256, GEMM_SMEM>>>(b_in, nullptr);

    // attention
    attn_mma<<<dim3(16, BHH), 128, ATTN_SMEM>>>(attn_bias, attn_mul, kpm);

    // output projection
    gemm_mma<1><<<dim3(8, 32), 256, GEMM_SMEM>>>(b_out, out);
}

// round 15
// speedup vs baseline: 1.8291x; 1.8291x over previous
#include <cuda_runtime.h>
#include <cuda_bf16.h>
#include <cstdint>

// Problem constants
#define SS 1024
#define BB 4
#define HH 16
#define DD 64
#define EE 1024
#define BHH 64   // B*H

// ---------------------------------------------------------------------------
// Scratch (device globals)
// ---------------------------------------------------------------------------
__device__ __nv_bfloat16 g_qhi[BHH * SS * DD], g_qlo[BHH * SS * DD];
__device__ __nv_bfloat16 g_khi[BHH * SS * DD], g_klo[BHH * SS * DD];
__device__ __nv_bfloat16 g_vhi[BHH * SS * DD], g_vlo[BHH * SS * DD];

__device__ __nv_bfloat16 g_xhi[4096 * 1024], g_xlo[4096 * 1024];
__device__ __nv_bfloat16 g_wihi[3072 * 1024], g_wilo[3072 * 1024];
__device__ __nv_bfloat16 g_wohi[1024 * 1024], g_wolo[1024 * 1024];
__device__ __nv_bfloat16 g_ahi[4096 * 1024], g_alo[4096 * 1024];

// ---------------------------------------------------------------------------
// Warp-level MMA helpers (baseline PTX, works on sm_103 non-'a' target)
// ---------------------------------------------------------------------------
__device__ __forceinline__ uint32_t smem_u32(const void* p) {
    uint32_t a;
    asm("{ .reg .u64 t; cvta.to.shared.u64 t, %1; cvt.u32.u64 %0, t; }"
        : "=r"(a) : "l"(p));
    return a;
}

__device__ __forceinline__ void ldm_x4(uint32_t* r, uint32_t addr) {
    asm volatile("ldmatrix.sync.aligned.m8n8.x4.shared.b16 {%0,%1,%2,%3}, [%4];"
                 : "=r"(r[0]), "=r"(r[1]), "=r"(r[2]), "=r"(r[3]) : "r"(addr));
}
__device__ __forceinline__ void ldm_x2(uint32_t* r, uint32_t addr) {
    asm volatile("ldmatrix.sync.aligned.m8n8.x2.shared.b16 {%0,%1}, [%2];"
                 : "=r"(r[0]), "=r"(r[1]) : "r"(addr));
}
__device__ __forceinline__ void ldm_x2t(uint32_t* r, uint32_t addr) {
    asm volatile("ldmatrix.sync.aligned.m8n8.x2.trans.shared.b16 {%0,%1}, [%2];"
                 : "=r"(r[0]), "=r"(r[1]) : "r"(addr));
}

// D(f32) += A(bf16) @ B(bf16), m16n8k16
__device__ __forceinline__ void mma_bf16(float* c, const uint32_t* a, const uint32_t* b) {
    asm volatile(
        "mma.sync.aligned.m16n8k16.row.col.f32.bf16.bf16.f32 "
        "{%0,%1,%2,%3}, {%4,%5,%6,%7}, {%8,%9}, {%0,%1,%2,%3};"
        : "+f"(c[0]), "+f"(c[1]), "+f"(c[2]), "+f"(c[3])
        : "r"(a[0]), "r"(a[1]), "r"(a[2]), "r"(a[3]), "r"(b[0]), "r"(b[1]));
}

// cp.async 16B
__device__ __forceinline__ void cp16(uint32_t dst, const void* src) {
    asm volatile("cp.async.cg.shared.global [%0], [%1], 16;" :: "r"(dst), "l"(src));
}
#define CP_COMMIT() asm volatile("cp.async.commit_group;" ::: "memory")
#define CP_WAIT(N)  asm volatile("cp.async.wait_group %0;" :: "n"(N) : "memory")

// pack two fp32 -> bf16x2 (x0 in low half, x1 in high half)
__device__ __forceinline__ uint32_t pack2(float x0, float x1) {
    uint32_t r;
    asm("cvt.rn.bf16x2.f32 %0, %1, %2;" : "=r"(r) : "f"(x1), "f"(x0));
    return r;
}
// split pair into hi/lo bf16x2
__device__ __forceinline__ void split2(float x0, float x1, uint32_t& hi, uint32_t& lo) {
    uint32_t hv = pack2(x0, x1);
    float h0 = __uint_as_float(hv << 16);
    float h1 = __uint_as_float(hv & 0xFFFF0000u);
    hi = hv;
    lo = pack2(x0 - h0, x1 - h1);
}

// ---------------------------------------------------------------------------
// fp32 -> bf16 hi/lo splits for x, W_in, W_out in ONE launch.
// blocks [0,4096): x | [4096,7168): W_in | [7168,8192): W_out
// ---------------------------------------------------------------------------
__global__ __launch_bounds__(256) void split_all(const float* __restrict__ x,
                                                 const float* __restrict__ wi,
                                                 const float* __restrict__ wo) {
    int bid = blockIdx.x;
    const float* src;
    __nv_bfloat16 *hi, *lo;
    int i;
    if (bid < 4096)      { src = x;  hi = g_xhi;  lo = g_xlo;  i = bid * 256 + threadIdx.x; }
    else if (bid < 7168) { src = wi; hi = g_wihi; lo = g_wilo; i = (bid - 4096) * 256 + threadIdx.x; }
    else                 { src = wo; hi = g_wohi; lo = g_wolo; i = (bid - 7168) * 256 + threadIdx.x; }

    float4 v = ((const float4*)src)[i];
    uint32_t h0, l0, h1, l1;
    split2(v.x, v.y, h0, l0);
    split2(v.z, v.w, h1, l1);
    ((uint2*)hi)[i] = make_uint2(h0, h1);
    ((uint2*)lo)[i] = make_uint2(l0, l1);
}

// ---------------------------------------------------------------------------
// mma.sync split-bf16 GEMM, cp.async double-buffered, SINGLE sync per K-tile:
//   CP_WAIT -> sync -> issue(kt+1 into other buffer) -> compute(kt)
// (top sync proves all warps finished reading the other buffer, so the issue
//  is safe and the trailing barrier is unnecessary)
// MODE 0: A=x(split), W=W_in(split) -> scatter bf16 hi/lo q/k/v (q*0.125)
// MODE 1: A=attn(split), W=W_out(split) -> write d_out (fp32)
// ---------------------------------------------------------------------------
#define BUF_U4 2560          // uint4 per buffer (4 arrays x 640)
#define ARR_U4 640

template <int MODE>
__global__ __launch_bounds__(256) void gemm_mma(
    const float* __restrict__ bias, float* __restrict__ Cout)
{
    extern __shared__ __align__(16) uint4 smem[];

    const __nv_bfloat16* Ahi = (MODE == 0) ? g_xhi  : g_ahi;
    const __nv_bfloat16* Alo = (MODE == 0) ? g_xlo  : g_alo;
    const __nv_bfloat16* Bhi = (MODE == 0) ? g_wihi : g_wohi;
    const __nv_bfloat16* Blo = (MODE == 0) ? g_wilo : g_wolo;

    const int tid = threadIdx.x;
    const int lane = tid & 31;
    const int wid = tid >> 5;
    const int wm = wid >> 2;
    const int wn = wid & 3;
    const int bm = blockIdx.y, bn = blockIdx.x;
    const int K = 1024;

    float acc[4][4][4];
#pragma unroll
    for (int mf = 0; mf < 4; mf++)
#pragma unroll
        for (int nf = 0; nf < 4; nf++)
#pragma unroll
            for (int e = 0; e < 4; e++) acc[mf][nf][e] = 0.f;

    const uint32_t uS = smem_u32(smem);
    const __nv_bfloat16* gsrc[4] = {Ahi, Alo, Bhi, Blo};

    auto issue = [&](int kt, int b) {
        const int k0 = kt * 32;
#pragma unroll
        for (int q = 0; q < 8; q++) {
            int a = q >> 1;
            int sub = (q & 1) * 256 + tid;
            int row = sub >> 2, kc = sub & 3;
            int gr = (a < 2 ? bm : bn) * 128 + row;
            const __nv_bfloat16* src = gsrc[a] + (size_t)gr * K + k0 + kc * 8;
            uint32_t dst = uS + (uint32_t)(b * BUF_U4 + a * ARR_U4 + row * 5 + kc) * 16u;
            cp16(dst, src);
        }
        CP_COMMIT();
    };

    const int a_row = wm * 64 + (lane & 7) + ((lane >> 3) & 1) * 8;
    const int a_kc  = (lane >> 4) & 1;
    const int b_row = wn * 32 + (lane & 7);
    const int b_kc  = (lane >> 3) & 1;

    issue(0, 0);

    for (int kt = 0; kt < 32; kt++) {
        const int b = kt & 1;
        CP_WAIT(0);            // tile kt is the only outstanding group
        __syncthreads();       // also proves buffer b^1 free for reuse
        if (kt < 31) issue(kt + 1, b ^ 1);

        const uint32_t uAhi = uS + (uint32_t)(b * BUF_U4) * 16u;
        const uint32_t uAlo = uAhi + ARR_U4 * 16u;
        const uint32_t uBhi = uAlo + ARR_U4 * 16u;
        const uint32_t uBlo = uBhi + ARR_U4 * 16u;

#pragma unroll
        for (int ks = 0; ks < 2; ks++) {
            uint32_t ah[4][4], al[4][4], bh[4][2], bl[4][2];
#pragma unroll
            for (int mf = 0; mf < 4; mf++) {
                uint32_t off = (uint32_t)(((a_row + mf * 16) * 5 + ks * 2 + a_kc) * 16);
                ldm_x4(ah[mf], uAhi + off);
                ldm_x4(al[mf], uAlo + off);
            }
#pragma unroll
            for (int nf = 0; nf < 4; nf++) {
                uint32_t off = (uint32_t)(((b_row + nf * 8) * 5 + ks * 2 + b_kc) * 16);
                ldm_x2(bh[nf], uBhi + off);
                ldm_x2(bl[nf], uBlo + off);
            }
#pragma unroll
            for (int mf = 0; mf < 4; mf++)
#pragma unroll
                for (int nf = 0; nf < 4; nf++) {
                    mma_bf16(acc[mf][nf], ah[mf], bh[nf]);
                    mma_bf16(acc[mf][nf], ah[mf], bl[nf]);
                    mma_bf16(acc[mf][nf], al[mf], bh[nf]);
                }
        }
        __syncthreads();   // all warps done reading buffer b before it refills
    }

#pragma unroll
    for (int mf = 0; mf < 4; mf++) {
#pragma unroll
        for (int nf = 0; nf < 4; nf++) {
#pragma unroll
            for (int e = 0; e < 4; e++) {
                int m = bm * 128 + wm * 64 + mf * 16 + (lane >> 2) + ((e >> 1) & 1) * 8;
                int n = bn * 128 + wn * 32 + nf * 8 + (lane & 3) * 2 + (e & 1);
                float v = acc[mf][nf][e] + bias[n];
                if (MODE == 0) {
                    int sidx = m >> 2;
                    int bt = m & 3;
                    int h = n / 192;
                    int rr = n - h * 192;
                    int bh2 = bt * HH + h;
                    __nv_bfloat16 *dh, *dl;
                    int dcol;
                    if (rr < 64)       { dh = g_qhi; dl = g_qlo; dcol = rr;       v *= 0.125f; }
                    else if (rr < 128) { dh = g_khi; dl = g_klo; dcol = rr - 64;  }
                    else               { dh = g_vhi; dl = g_vlo; dcol = rr - 128; }
                    size_t idx = ((size_t)bh2 * SS + sidx) * DD + dcol;
                    __nv_bfloat16 hv = __float2bfloat16(v);
                    __nv_bfloat16 lv = __float2bfloat16(v - __bfloat162float(hv));
                    dh[idx] = hv;
                    dl[idx] = lv;
                } else {
                    Cout[(size_t)m * 1024 + n] = v;
                }
            }
        }
    }
}

// ---------------------------------------------------------------------------
// Flash attention on mma.sync (round-12 proven body); K/V staged via cp.async
// overlapped with the bias/mul mask-fold staging.
// ---------------------------------------------------------------------------
#define TSWZ(row, ch) ((((row)) << 7) + ((((ch) ^ ((row) & 7))) << 4))
#define SBP 68

__global__ __launch_bounds__(128) void attn_mma(
    const float* __restrict__ bias_g, const float* __restrict__ mul_g,
    const int* __restrict__ kpm)
{
    extern __shared__ uint8_t sm[];
    float* sB = (float*)(sm + 32768);
    float* sM = (float*)(sm + 50176);

    const int tid = threadIdx.x;
    const int lane = tid & 31;
    const int warp = tid >> 5;
    const int qt = blockIdx.x, bh = blockIdx.y;
    const int b = bh >> 4, h = bh & 15;
    const uint32_t uSm = smem_u32(sm);

    const __nv_bfloat16* qhi = g_qhi + ((size_t)bh * SS + qt * 64) * DD;
    const __nv_bfloat16* qlo = g_qlo + ((size_t)bh * SS + qt * 64) * DD;
    const __nv_bfloat16* khi = g_khi + (size_t)bh * SS * DD;
    const __nv_bfloat16* klo = g_klo + (size_t)bh * SS * DD;
    const __nv_bfloat16* vhi = g_vhi + (size_t)bh * SS * DD;
    const __nv_bfloat16* vlo = g_vlo + (size_t)bh * SS * DD;
    const float* bbase = bias_g + ((size_t)bh * SS + qt * 64) * SS;
    const float* mbase = mul_g + ((size_t)bh * SS + qt * 64) * SS;
    const int* kp = kpm + b * SS;

    // ---- stage Q into smem (at sB region), load A-fragments, then free it
#pragma unroll
    for (int t = 0; t < 4; t++) {
        int idx = tid + t * 128;
        int row = idx >> 3, ch = idx & 7;
        *(uint4*)(sm + 32768 + TSWZ(row, ch)) = *(const uint4*)(qhi + row * 64 + ch * 8);
        *(uint4*)(sm + 40960 + TSWZ(row, ch)) = *(const uint4*)(qlo + row * 64 + ch * 8);
    }
    __syncthreads();

    uint32_t qh[4][4], ql[4][4];
    {
        int arow = warp * 16 + (lane & 7) + ((lane >> 3) & 1) * 8;
        int akc = (lane >> 4) & 1;
#pragma unroll
        for (int ds = 0; ds < 4; ds++) {
            uint32_t off = (uint32_t)TSWZ(arow, ds * 2 + akc);
            ldm_x4(qh[ds], uSm + 32768 + off);
            ldm_x4(ql[ds], uSm + 40960 + off);
        }
    }

    float acc[8][4];
#pragma unroll
    for (int i = 0; i < 8; i++)
#pragma unroll
        for (int e = 0; e < 4; e++) acc[i][e] = 0.f;
    float m0 = 0.f, m1 = 0.f, l0 = 1.f, l1 = 1.f;   // phantom logit 0

    const int r0 = warp * 16 + (lane >> 2);
    const int cc = (lane & 3) * 2;
    const int brow = lane & 7;
    const int bkc = (lane >> 3) & 1;
    const int vrow = (lane & 7) + ((lane >> 3) & 1) * 8;

    for (int kt = 0; kt < 16; kt++) {
        const int k0 = kt * 64;
        __syncthreads();   // all warps done with previous tile's smem

        // K/V hi/lo via cp.async (flies while we fold the mask below)
#pragma unroll
        for (int t = 0; t < 4; t++) {
            int idx = tid + t * 128;
            int row = idx >> 3, ch = idx & 7;
            size_t go = (size_t)(k0 + row) * 64 + ch * 8;
            uint32_t so = TSWZ(row, ch);
            cp16(uSm + so,         khi + go);
            cp16(uSm + 8192 + so,  klo + go);
            cp16(uSm + 16384 + so, vhi + go);
            cp16(uSm + 24576 + so, vlo + go);
        }
        CP_COMMIT();

        // stage bias/mul with mask folded in (blocking; overlaps the cp.async)
#pragma unroll
        for (int t = 0; t < 8; t++) {
            int idx = tid + t * 128;
            int row = idx >> 4, c4 = idx & 15;
            int col = c4 * 4;
            int4 mk = *(const int4*)(kp + k0 + col);
            float4 bv = *(const float4*)(bbase + (size_t)row * SS + k0 + col);
            float4 mv = *(const float4*)(mbase + (size_t)row * SS + k0 + col);
            if (mk.x) { bv.x = -1e30f; mv.x = 0.f; }
            if (mk.y) { bv.y = -1e30f; mv.y = 0.f; }
            if (mk.z) { bv.z = -1e30f; mv.z = 0.f; }
            if (mk.w) { bv.w = -1e30f; mv.w = 0.f; }
            *(float4*)&sB[row * SBP + col] = bv;
            *(float4*)&sM[row * SBP + col] = mv;
        }
        CP_WAIT(0);
        __syncthreads();

        // ---- S = bias + Q K^T (3-term)
        float s[8][4];
#pragma unroll
        for (int nf = 0; nf < 8; nf++) {
            float2 t0 = *(float2*)&sB[r0 * SBP + nf * 8 + cc];
            float2 t1 = *(float2*)&sB[(r0 + 8) * SBP + nf * 8 + cc];
            s[nf][0] = t0.x; s[nf][1] = t0.y; s[nf][2] = t1.x; s[nf][3] = t1.y;
        }
#pragma unroll
        for (int ds = 0; ds < 4; ds++) {
#pragma unroll
            for (int nf = 0; nf < 8; nf++) {
                uint32_t kh2[2], kl2[2];
                uint32_t off = (uint32_t)TSWZ(nf * 8 + brow, ds * 2 + bkc);
                ldm_x2(kh2, uSm + off);
                ldm_x2(kl2, uSm + 8192 + off);
                mma_bf16(s[nf], qh[ds], kh2);
                mma_bf16(s[nf], qh[ds], kl2);
                mma_bf16(s[nf], ql[ds], kh2);
            }
        }

        // ---- online softmax_1
        float tm0 = s[0][0], tm1 = s[0][2];
#pragma unroll
        for (int nf = 0; nf < 8; nf++) {
            tm0 = fmaxf(tm0, fmaxf(s[nf][0], s[nf][1]));
            tm1 = fmaxf(tm1, fmaxf(s[nf][2], s[nf][3]));
        }
        tm0 = fmaxf(tm0, __shfl_xor_sync(0xffffffffu, tm0, 1));
        tm0 = fmaxf(tm0, __shfl_xor_sync(0xffffffffu, tm0, 2));
        tm1 = fmaxf(tm1, __shfl_xor_sync(0xffffffffu, tm1, 1));
        tm1 = fmaxf(tm1, __shfl_xor_sync(0xffffffffu, tm1, 2));
        float mn0 = fmaxf(m0, tm0), mn1 = fmaxf(m1, tm1);
        float sc0 = __expf(m0 - mn0), sc1 = __expf(m1 - mn1);
        m0 = mn0; m1 = mn1;
        float rs0 = 0.f, rs1 = 0.f;
#pragma unroll
        for (int nf = 0; nf < 8; nf++) {
            s[nf][0] = __expf(s[nf][0] - mn0);
            s[nf][1] = __expf(s[nf][1] - mn0);
            s[nf][2] = __expf(s[nf][2] - mn1);
            s[nf][3] = __expf(s[nf][3] - mn1);
            rs0 += s[nf][0] + s[nf][1];
            rs1 += s[nf][2] + s[nf][3];
        }
        rs0 += __shfl_xor_sync(0xffffffffu, rs0, 1);
        rs0 += __shfl_xor_sync(0xffffffffu, rs0, 2);
        rs1 += __shfl_xor_sync(0xffffffffu, rs1, 1);
        rs1 += __shfl_xor_sync(0xffffffffu, rs1, 2);
        l0 = l0 * sc0 + rs0;
        l1 = l1 * sc1 + rs1;
#pragma unroll
        for (int i = 0; i < 8; i++) {
            acc[i][0] *= sc0; acc[i][1] *= sc0;
            acc[i][2] *= sc1; acc[i][3] *= sc1;
        }

        // ---- p *= abm
#pragma unroll
        for (int nf = 0; nf < 8; nf++) {
            float2 t0 = *(float2*)&sM[r0 * SBP + nf * 8 + cc];
            float2 t1 = *(float2*)&sM[(r0 + 8) * SBP + nf * 8 + cc];
            s[nf][0] *= t0.x; s[nf][1] *= t0.y; s[nf][2] *= t1.x; s[nf][3] *= t1.y;
        }

        // ---- acc += P V (3-term)
#pragma unroll
        for (int ks = 0; ks < 4; ks++) {
            uint32_t ahi[4], alo[4];
            split2(s[2 * ks][0],     s[2 * ks][1],     ahi[0], alo[0]);
            split2(s[2 * ks][2],     s[2 * ks][3],     ahi[1], alo[1]);
            split2(s[2 * ks + 1][0], s[2 * ks + 1][1], ahi[2], alo[2]);
            split2(s[2 * ks + 1][2], s[2 * ks + 1][3], ahi[3], alo[3]);
#pragma unroll
            for (int nfd = 0; nfd < 8; nfd++) {
                uint32_t vh2[2], vl2[2];
                uint32_t off = (uint32_t)TSWZ(ks * 16 + vrow, nfd);
                ldm_x2t(vh2, uSm + 16384 + off);
                ldm_x2t(vl2, uSm + 24576 + off);
                mma_bf16(acc[nfd], ahi, vh2);
                mma_bf16(acc[nfd], ahi, vl2);
                mma_bf16(acc[nfd], alo, vh2);
            }
        }
    }

    // ---- epilogue
    float inv0 = 1.0f / l0, inv1 = 1.0f / l1;
    int q0 = qt * 64 + r0;
    size_t o0 = ((size_t)q0 * BB + b) * EE + h * 64;
    size_t o1 = ((size_t)(q0 + 8) * BB + b) * EE + h * 64;
#pragma unroll
    for (int nfd = 0; nfd < 8; nfd++) {
        int dc = nfd * 8 + cc;
        uint32_t h0, lo0, h1, lo1;
        split2(acc[nfd][0] * inv0, acc[nfd][1] * inv0, h0, lo0);
        split2(acc[nfd][2] * inv1, acc[nfd][3] * inv1, h1, lo1);
        *(uint32_t*)(g_ahi + o0 + dc) = h0;
        *(uint32_t*)(g_alo + o0 + dc) = lo0;
        *(uint32_t*)(g_ahi + o1 + dc) = h1;
        *(uint32_t*)(g_alo + o1 + dc) = lo1;
    }
}

// ---------------------------------------------------------------------------
extern "C" void kernel_launch(void* const* d_in, const int* in_sizes, int n_in,
                              void* d_out, int out_size)
{
    (void)in_sizes; (void)n_in; (void)out_size;
    const float* x         = (const float*)d_in[0];
    const float* attn_bias = (const float*)d_in[1];
    const float* attn_mul  = (const float*)d_in[2];
    const int*   kpm       = (const int*)d_in[3];
    const float* W_in      = (const float*)d_in[4];
    const float* b_in      = (const float*)d_in[5];
    const float* W_out     = (const float*)d_in[6];
    const float* b_out     = (const float*)d_in[7];
    float* out = (float*)d_out;

    const int GEMM_SMEM = 81920;
    const int ATTN_SMEM = 67584;
    cudaFuncSetAttribute(gemm_mma<0>, cudaFuncAttributeMaxDynamicSharedMemorySize, GEMM_SMEM);
    cudaFuncSetAttribute(gemm_mma<1>, cudaFuncAttributeMaxDynamicSharedMemorySize, GEMM_SMEM);
    cudaFuncSetAttribute(attn_mma, cudaFuncAttributeMaxDynamicSharedMemorySize, ATTN_SMEM);

    // fp32 -> bf16 hi/lo splits (single launch)
    split_all<<<8192, 256>>>(x, W_in, W_out);

    // QKV projection
    gemm_mma<0><<<dim3(24, 32), 256, GEMM_SMEM>>>(b_in, nullptr);

    // attention
    attn_mma<<<dim3(16, BHH), 128, ATTN_SMEM>>>(attn_bias, attn_mul, kpm);

    // output projection
    gemm_mma<1><<<dim3(8, 32), 256, GEMM_SMEM>>>(b_out, out);
}

// round 16
// speedup vs baseline: 1.8423x; 1.0072x over previous
#include <cuda_runtime.h>
#include <cuda_bf16.h>
#include <cstdint>

// Problem constants
#define SS 1024
#define BB 4
#define HH 16
#define DD 64
#define EE 1024
#define BHH 64   // B*H

// ---------------------------------------------------------------------------
// Scratch (device globals)
// ---------------------------------------------------------------------------
__device__ __nv_bfloat16 g_qhi[BHH * SS * DD], g_qlo[BHH * SS * DD];
__device__ __nv_bfloat16 g_khi[BHH * SS * DD], g_klo[BHH * SS * DD];
__device__ __nv_bfloat16 g_vhi[BHH * SS * DD], g_vlo[BHH * SS * DD];

__device__ __nv_bfloat16 g_xhi[4096 * 1024], g_xlo[4096 * 1024];
__device__ __nv_bfloat16 g_wihi[3072 * 1024], g_wilo[3072 * 1024];
__device__ __nv_bfloat16 g_wohi[1024 * 1024], g_wolo[1024 * 1024];
__device__ __nv_bfloat16 g_ahi[4096 * 1024], g_alo[4096 * 1024];

// ---------------------------------------------------------------------------
// Warp-level MMA helpers (baseline PTX, works on sm_103 non-'a' target)
// ---------------------------------------------------------------------------
__device__ __forceinline__ uint32_t smem_u32(const void* p) {
    uint32_t a;
    asm("{ .reg .u64 t; cvta.to.shared.u64 t, %1; cvt.u32.u64 %0, t; }"
        : "=r"(a) : "l"(p));
    return a;
}

__device__ __forceinline__ void ldm_x4(uint32_t* r, uint32_t addr) {
    asm volatile("ldmatrix.sync.aligned.m8n8.x4.shared.b16 {%0,%1,%2,%3}, [%4];"
                 : "=r"(r[0]), "=r"(r[1]), "=r"(r[2]), "=r"(r[3]) : "r"(addr));
}
__device__ __forceinline__ void ldm_x2(uint32_t* r, uint32_t addr) {
    asm volatile("ldmatrix.sync.aligned.m8n8.x2.shared.b16 {%0,%1}, [%2];"
                 : "=r"(r[0]), "=r"(r[1]) : "r"(addr));
}
__device__ __forceinline__ void ldm_x2t(uint32_t* r, uint32_t addr) {
    asm volatile("ldmatrix.sync.aligned.m8n8.x2.trans.shared.b16 {%0,%1}, [%2];"
                 : "=r"(r[0]), "=r"(r[1]) : "r"(addr));
}

// D(f32) += A(bf16) @ B(bf16), m16n8k16
__device__ __forceinline__ void mma_bf16(float* c, const uint32_t* a, const uint32_t* b) {
    asm volatile(
        "mma.sync.aligned.m16n8k16.row.col.f32.bf16.bf16.f32 "
        "{%0,%1,%2,%3}, {%4,%5,%6,%7}, {%8,%9}, {%0,%1,%2,%3};"
        : "+f"(c[0]), "+f"(c[1]), "+f"(c[2]), "+f"(c[3])
        : "r"(a[0]), "r"(a[1]), "r"(a[2]), "r"(a[3]), "r"(b[0]), "r"(b[1]));
}

// cp.async 16B
__device__ __forceinline__ void cp16(uint32_t dst, const void* src) {
    asm volatile("cp.async.cg.shared.global [%0], [%1], 16;" :: "r"(dst), "l"(src));
}
#define CP_COMMIT() asm volatile("cp.async.commit_group;" ::: "memory")
#define CP_WAIT(N)  asm volatile("cp.async.wait_group %0;" :: "n"(N) : "memory")

// pack two fp32 -> bf16x2 (x0 in low half, x1 in high half)
__device__ __forceinline__ uint32_t pack2(float x0, float x1) {
    uint32_t r;
    asm("cvt.rn.bf16x2.f32 %0, %1, %2;" : "=r"(r) : "f"(x1), "f"(x0));
    return r;
}
// split pair into hi/lo bf16x2
__device__ __forceinline__ void split2(float x0, float x1, uint32_t& hi, uint32_t& lo) {
    uint32_t hv = pack2(x0, x1);
    float h0 = __uint_as_float(hv << 16);
    float h1 = __uint_as_float(hv & 0xFFFF0000u);
    hi = hv;
    lo = pack2(x0 - h0, x1 - h1);
}

// ---------------------------------------------------------------------------
// fp32 -> bf16 hi/lo splits for x, W_in, W_out in ONE launch.
// blocks [0,4096): x | [4096,7168): W_in | [7168,8192): W_out
// ---------------------------------------------------------------------------
__global__ __launch_bounds__(256) void split_all(const float* __restrict__ x,
                                                 const float* __restrict__ wi,
                                                 const float* __restrict__ wo) {
    int bid = blockIdx.x;
    const float* src;
    __nv_bfloat16 *hi, *lo;
    int i;
    if (bid < 4096)      { src = x;  hi = g_xhi;  lo = g_xlo;  i = bid * 256 + threadIdx.x; }
    else if (bid < 7168) { src = wi; hi = g_wihi; lo = g_wilo; i = (bid - 4096) * 256 + threadIdx.x; }
    else                 { src = wo; hi = g_wohi; lo = g_wolo; i = (bid - 7168) * 256 + threadIdx.x; }

    float4 v = ((const float4*)src)[i];
    uint32_t h0, l0, h1, l1;
    split2(v.x, v.y, h0, l0);
    split2(v.z, v.w, h1, l1);
    ((uint2*)hi)[i] = make_uint2(h0, h1);
    ((uint2*)lo)[i] = make_uint2(l0, l1);
}

// ---------------------------------------------------------------------------
// mma.sync split-bf16 GEMM, CTA tile 64x128 (3 CTAs/SM), cp.async
// double-buffered, single sync per K-tile.
// 8 warps (2x4), warp tile 32x32 (mf=2 x nf=4 frags).
// Smem per buffer (pitch-5 rows, u4 units): Ahi 320 | Alo 320 | Bhi 640 |
// Blo 640 = 1920 u4 = 30 KB; two buffers = 60 KB.
// MODE 0: A=x(split), W=W_in(split) -> scatter bf16 hi/lo q/k/v (q*0.125)
// MODE 1: A=attn(split), W=W_out(split) -> write d_out (fp32)
// ---------------------------------------------------------------------------
#define GBUF_U4 1920

template <int MODE>
__global__ __launch_bounds__(256, 3) void gemm_mma(
    const float* __restrict__ bias, float* __restrict__ Cout)
{
    extern __shared__ __align__(16) uint4 smem[];

    const __nv_bfloat16* Ahi = (MODE == 0) ? g_xhi  : g_ahi;
    const __nv_bfloat16* Alo = (MODE == 0) ? g_xlo  : g_alo;
    const __nv_bfloat16* Bhi = (MODE == 0) ? g_wihi : g_wohi;
    const __nv_bfloat16* Blo = (MODE == 0) ? g_wilo : g_wolo;

    const int tid = threadIdx.x;
    const int lane = tid & 31;
    const int wid = tid >> 5;
    const int wm = wid >> 2;        // 0..1 (32-row slabs)
    const int wn = wid & 3;         // 0..3 (32-col slabs)
    const int bm = blockIdx.y, bn = blockIdx.x;
    const int K = 1024;

    float acc[2][4][4];
#pragma unroll
    for (int mf = 0; mf < 2; mf++)
#pragma unroll
        for (int nf = 0; nf < 4; nf++)
#pragma unroll
            for (int e = 0; e < 4; e++) acc[mf][nf][e] = 0.f;

    const uint32_t uS = smem_u32(smem);
    const __nv_bfloat16* gsrc[4] = {Ahi, Alo, Bhi, Blo};
    // array offsets within a buffer (u4): Ahi 0, Alo 320, Bhi 640, Blo 1280
    // data u4 per array: A 256 (64 rows x 4), B 512 (128 rows x 4); total 1536.

    auto issue = [&](int kt, int b) {
        const int k0 = kt * 32;
#pragma unroll
        for (int q = 0; q < 6; q++) {
            int c = q * 256 + tid;
            int a, d;
            if (c < 256)       { a = 0; d = c; }
            else if (c < 512)  { a = 1; d = c - 256; }
            else if (c < 1024) { a = 2; d = c - 512; }
            else               { a = 3; d = c - 1024; }
            int row = d >> 2, kc = d & 3;
            int gr = (a < 2) ? (bm * 64 + row) : (bn * 128 + row);
            int arrOff = (a == 0) ? 0 : (a == 1) ? 320 : (a == 2) ? 640 : 1280;
            const __nv_bfloat16* src = gsrc[a] + (size_t)gr * K + k0 + kc * 8;
            uint32_t dst = uS + (uint32_t)(b * GBUF_U4 + arrOff + row * 5 + kc) * 16u;
            cp16(dst, src);
        }
        CP_COMMIT();
    };

    const int a_row = wm * 32 + (lane & 7) + ((lane >> 3) & 1) * 8;   // + mf*16
    const int a_kc  = (lane >> 4) & 1;
    const int b_row = wn * 32 + (lane & 7);                            // + nf*8
    const int b_kc  = (lane >> 3) & 1;

    issue(0, 0);

    for (int kt = 0; kt < 32; kt++) {
        const int b = kt & 1;
        CP_WAIT(0);            // tile kt is the only outstanding group
        __syncthreads();       // copies visible; peer buffer drained
        if (kt < 31) issue(kt + 1, b ^ 1);

        const uint32_t uAhi = uS + (uint32_t)(b * GBUF_U4) * 16u;
        const uint32_t uAlo = uAhi + 320u * 16u;
        const uint32_t uBhi = uAhi + 640u * 16u;
        const uint32_t uBlo = uAhi + 1280u * 16u;

#pragma unroll
        for (int ks = 0; ks < 2; ks++) {
            uint32_t ah[2][4], al[2][4], bh[4][2], bl[4][2];
#pragma unroll
            for (int mf = 0; mf < 2; mf++) {
                uint32_t off = (uint32_t)(((a_row + mf * 16) * 5 + ks * 2 + a_kc) * 16);
                ldm_x4(ah[mf], uAhi + off);
                ldm_x4(al[mf], uAlo + off);
            }
#pragma unroll
            for (int nf = 0; nf < 4; nf++) {
                uint32_t off = (uint32_t)(((b_row + nf * 8) * 5 + ks * 2 + b_kc) * 16);
                ldm_x2(bh[nf], uBhi + off);
                ldm_x2(bl[nf], uBlo + off);
            }
#pragma unroll
            for (int mf = 0; mf < 2; mf++)
#pragma unroll
                for (int nf = 0; nf < 4; nf++) {
                    mma_bf16(acc[mf][nf], ah[mf], bh[nf]);
                    mma_bf16(acc[mf][nf], ah[mf], bl[nf]);
                    mma_bf16(acc[mf][nf], al[mf], bh[nf]);
                }
        }
        // no trailing sync: next iteration's top sync (after CP_WAIT) protects
        // the buffer before it is re-issued.
    }

#pragma unroll
    for (int mf = 0; mf < 2; mf++) {
#pragma unroll
        for (int nf = 0; nf < 4; nf++) {
#pragma unroll
            for (int e = 0; e < 4; e++) {
                int m = bm * 64 + wm * 32 + mf * 16 + (lane >> 2) + ((e >> 1) & 1) * 8;
                int n = bn * 128 + wn * 32 + nf * 8 + (lane & 3) * 2 + (e & 1);
                float v = acc[mf][nf][e] + bias[n];
                if (MODE == 0) {
                    int sidx = m >> 2;
                    int bt = m & 3;
                    int h = n / 192;
                    int rr = n - h * 192;
                    int bh2 = bt * HH + h;
                    __nv_bfloat16 *dh, *dl;
                    int dcol;
                    if (rr < 64)       { dh = g_qhi; dl = g_qlo; dcol = rr;       v *= 0.125f; }
                    else if (rr < 128) { dh = g_khi; dl = g_klo; dcol = rr - 64;  }
                    else               { dh = g_vhi; dl = g_vlo; dcol = rr - 128; }
                    size_t idx = ((size_t)bh2 * SS + sidx) * DD + dcol;
                    __nv_bfloat16 hv = __float2bfloat16(v);
                    __nv_bfloat16 lv = __float2bfloat16(v - __bfloat162float(hv));
                    dh[idx] = hv;
                    dl[idx] = lv;
                } else {
                    Cout[(size_t)m * 1024 + n] = v;
                }
            }
        }
    }
}

// ---------------------------------------------------------------------------
// Flash attention on mma.sync (round-15 proven body): K/V staged via cp.async
// overlapped with the bias/mul mask-fold staging.
// ---------------------------------------------------------------------------
#define TSWZ(row, ch) ((((row)) << 7) + ((((ch) ^ ((row) & 7))) << 4))
#define SBP 68

__global__ __launch_bounds__(128) void attn_mma(
    const float* __restrict__ bias_g, const float* __restrict__ mul_g,
    const int* __restrict__ kpm)
{
    extern __shared__ uint8_t sm[];
    float* sB = (float*)(sm + 32768);
    float* sM = (float*)(sm + 50176);

    const int tid = threadIdx.x;
    const int lane = tid & 31;
    const int warp = tid >> 5;
    const int qt = blockIdx.x, bh = blockIdx.y;
    const int b = bh >> 4, h = bh & 15;
    const uint32_t uSm = smem_u32(sm);

    const __nv_bfloat16* qhi = g_qhi + ((size_t)bh * SS + qt * 64) * DD;
    const __nv_bfloat16* qlo = g_qlo + ((size_t)bh * SS + qt * 64) * DD;
    const __nv_bfloat16* khi = g_khi + (size_t)bh * SS * DD;
    const __nv_bfloat16* klo = g_klo + (size_t)bh * SS * DD;
    const __nv_bfloat16* vhi = g_vhi + (size_t)bh * SS * DD;
    const __nv_bfloat16* vlo = g_vlo + (size_t)bh * SS * DD;
    const float* bbase = bias_g + ((size_t)bh * SS + qt * 64) * SS;
    const float* mbase = mul_g + ((size_t)bh * SS + qt * 64) * SS;
    const int* kp = kpm + b * SS;

    // ---- stage Q into smem (at sB region), load A-fragments, then free it
#pragma unroll
    for (int t = 0; t < 4; t++) {
        int idx = tid + t * 128;
        int row = idx >> 3, ch = idx & 7;
        *(uint4*)(sm + 32768 + TSWZ(row, ch)) = *(const uint4*)(qhi + row * 64 + ch * 8);
        *(uint4*)(sm + 40960 + TSWZ(row, ch)) = *(const uint4*)(qlo + row * 64 + ch * 8);
    }
    __syncthreads();

    uint32_t qh[4][4], ql[4][4];
    {
        int arow = warp * 16 + (lane & 7) + ((lane >> 3) & 1) * 8;
        int akc = (lane >> 4) & 1;
#pragma unroll
        for (int ds = 0; ds < 4; ds++) {
            uint32_t off = (uint32_t)TSWZ(arow, ds * 2 + akc);
            ldm_x4(qh[ds], uSm + 32768 + off);
            ldm_x4(ql[ds], uSm + 40960 + off);
        }
    }

    float acc[8][4];
#pragma unroll
    for (int i = 0; i < 8; i++)
#pragma unroll
        for (int e = 0; e < 4; e++) acc[i][e] = 0.f;
    float m0 = 0.f, m1 = 0.f, l0 = 1.f, l1 = 1.f;   // phantom logit 0

    const int r0 = warp * 16 + (lane >> 2);
    const int cc = (lane & 3) * 2;
    const int brow = lane & 7;
    const int bkc = (lane >> 3) & 1;
    const int vrow = (lane & 7) + ((lane >> 3) & 1) * 8;

    for (int kt = 0; kt < 16; kt++) {
        const int k0 = kt * 64;
        __syncthreads();   // all warps done with previous tile's smem

        // K/V hi/lo via cp.async (flies while we fold the mask below)
#pragma unroll
        for (int t = 0; t < 4; t++) {
            int idx = tid + t * 128;
            int row = idx >> 3, ch = idx & 7;
            size_t go = (size_t)(k0 + row) * 64 + ch * 8;
            uint32_t so = TSWZ(row, ch);
            cp16(uSm + so,         khi + go);
            cp16(uSm + 8192 + so,  klo + go);
            cp16(uSm + 16384 + so, vhi + go);
            cp16(uSm + 24576 + so, vlo + go);
        }
        CP_COMMIT();

        // stage bias/mul with mask folded in (blocking; overlaps the cp.async)
#pragma unroll
        for (int t = 0; t < 8; t++) {
            int idx = tid + t * 128;
            int row = idx >> 4, c4 = idx & 15;
            int col = c4 * 4;
            int4 mk = *(const int4*)(kp + k0 + col);
            float4 bv = *(const float4*)(bbase + (size_t)row * SS + k0 + col);
            float4 mv = *(const float4*)(mbase + (size_t)row * SS + k0 + col);
            if (mk.x) { bv.x = -1e30f; mv.x = 0.f; }
            if (mk.y) { bv.y = -1e30f; mv.y = 0.f; }
            if (mk.z) { bv.z = -1e30f; mv.z = 0.f; }
            if (mk.w) { bv.w = -1e30f; mv.w = 0.f; }
            *(float4*)&sB[row * SBP + col] = bv;
            *(float4*)&sM[row * SBP + col] = mv;
        }
        CP_WAIT(0);
        __syncthreads();

        // ---- S = bias + Q K^T (3-term)
        float s[8][4];
#pragma unroll
        for (int nf = 0; nf < 8; nf++) {
            float2 t0 = *(float2*)&sB[r0 * SBP + nf * 8 + cc];
            float2 t1 = *(float2*)&sB[(r0 + 8) * SBP + nf * 8 + cc];
            s[nf][0] = t0.x; s[nf][1] = t0.y; s[nf][2] = t1.x; s[nf][3] = t1.y;
        }
#pragma unroll
        for (int ds = 0; ds < 4; ds++) {
#pragma unroll
            for (int nf = 0; nf < 8; nf++) {
                uint32_t kh2[2], kl2[2];
                uint32_t off = (uint32_t)TSWZ(nf * 8 + brow, ds * 2 + bkc);
                ldm_x2(kh2, uSm + off);
                ldm_x2(kl2, uSm + 8192 + off);
                mma_bf16(s[nf], qh[ds], kh2);
                mma_bf16(s[nf], qh[ds], kl2);
                mma_bf16(s[nf], ql[ds], kh2);
            }
        }

        // ---- online softmax_1
        float tm0 = s[0][0], tm1 = s[0][2];
#pragma unroll
        for (int nf = 0; nf < 8; nf++) {
            tm0 = fmaxf(tm0, fmaxf(s[nf][0], s[nf][1]));
            tm1 = fmaxf(tm1, fmaxf(s[nf][2], s[nf][3]));
        }
        tm0 = fmaxf(tm0, __shfl_xor_sync(0xffffffffu, tm0, 1));
        tm0 = fmaxf(tm0, __shfl_xor_sync(0xffffffffu, tm0, 2));
        tm1 = fmaxf(tm1, __shfl_xor_sync(0xffffffffu, tm1, 1));
        tm1 = fmaxf(tm1, __shfl_xor_sync(0xffffffffu, tm1, 2));
        float mn0 = fmaxf(m0, tm0), mn1 = fmaxf(m1, tm1);
        float sc0 = __expf(m0 - mn0), sc1 = __expf(m1 - mn1);
        m0 = mn0; m1 = mn1;
        float rs0 = 0.f, rs1 = 0.f;
#pragma unroll
        for (int nf = 0; nf < 8; nf++) {
            s[nf][0] = __expf(s[nf][0] - mn0);
            s[nf][1] = __expf(s[nf][1] - mn0);
            s[nf][2] = __expf(s[nf][2] - mn1);
            s[nf][3] = __expf(s[nf][3] - mn1);
            rs0 += s[nf][0] + s[nf][1];
            rs1 += s[nf][2] + s[nf][3];
        }
        rs0 += __shfl_xor_sync(0xffffffffu, rs0, 1);
        rs0 += __shfl_xor_sync(0xffffffffu, rs0, 2);
        rs1 += __shfl_xor_sync(0xffffffffu, rs1, 1);
        rs1 += __shfl_xor_sync(0xffffffffu, rs1, 2);
        l0 = l0 * sc0 + rs0;
        l1 = l1 * sc1 + rs1;
#pragma unroll
        for (int i = 0; i < 8; i++) {
            acc[i][0] *= sc0; acc[i][1] *= sc0;
            acc[i][2] *= sc1; acc[i][3] *= sc1;
        }

        // ---- p *= abm
#pragma unroll
        for (int nf = 0; nf < 8; nf++) {
            float2 t0 = *(float2*)&sM[r0 * SBP + nf * 8 + cc];
            float2 t1 = *(float2*)&sM[(r0 + 8) * SBP + nf * 8 + cc];
            s[nf][0] *= t0.x; s[nf][1] *= t0.y; s[nf][2] *= t1.x; s[nf][3] *= t1.y;
        }

        // ---- acc += P V (3-term)
#pragma unroll
        for (int ks = 0; ks < 4; ks++) {
            uint32_t ahi[4], alo[4];
            split2(s[2 * ks][0],     s[2 * ks][1],     ahi[0], alo[0]);
            split2(s[2 * ks][2],     s[2 * ks][3],     ahi[1], alo[1]);
            split2(s[2 * ks + 1][0], s[2 * ks + 1][1], ahi[2], alo[2]);
            split2(s[2 * ks + 1][2], s[2 * ks + 1][3], ahi[3], alo[3]);
#pragma unroll
            for (int nfd = 0; nfd < 8; nfd++) {
                uint32_t vh2[2], vl2[2];
                uint32_t off = (uint32_t)TSWZ(ks * 16 + vrow, nfd);
                ldm_x2t(vh2, uSm + 16384 + off);
                ldm_x2t(vl2, uSm + 24576 + off);
                mma_bf16(acc[nfd], ahi, vh2);
                mma_bf16(acc[nfd], ahi, vl2);
                mma_bf16(acc[nfd], alo, vh2);
            }
        }
    }

    // ---- epilogue
    float inv0 = 1.0f / l0, inv1 = 1.0f / l1;
    int q0 = qt * 64 + r0;
    size_t o0 = ((size_t)q0 * BB + b) * EE + h * 64;
    size_t o1 = ((size_t)(q0 + 8) * BB + b) * EE + h * 64;
#pragma unroll
    for (int nfd = 0; nfd < 8; nfd++) {
        int dc = nfd * 8 + cc;
        uint32_t h0, lo0, h1, lo1;
        split2(acc[nfd][0] * inv0, acc[nfd][1] * inv0, h0, lo0);
        split2(acc[nfd][2] * inv1, acc[nfd][3] * inv1, h1, lo1);
        *(uint32_t*)(g_ahi + o0 + dc) = h0;
        *(uint32_t*)(g_alo + o0 + dc) = lo0;
        *(uint32_t*)(g_ahi + o1 + dc) = h1;
        *(uint32_t*)(g_alo + o1 + dc) = lo1;
    }
}

// ---------------------------------------------------------------------------
extern "C" void kernel_launch(void* const* d_in, const int* in_sizes, int n_in,
                              void* d_out, int out_size)
{
    (void)in_sizes; (void)n_in; (void)out_size;
    const float* x         = (const float*)d_in[0];
    const float* attn_bias = (const float*)d_in[1];
    const float* attn_mul  = (const float*)d_in[2];
    const int*   kpm       = (const int*)d_in[3];
    const float* W_in      = (const float*)d_in[4];
    const float* b_in      = (const float*)d_in[5];
    const float* W_out     = (const float*)d_in[6];
    const float* b_out     = (const float*)d_in[7];
    float* out = (float*)d_out;

    const int GEMM_SMEM = 2 * GBUF_U4 * 16;   // 61440
    const int ATTN_SMEM = 67584;
    cudaFuncSetAttribute(gemm_mma<0>, cudaFuncAttributeMaxDynamicSharedMemorySize, GEMM_SMEM);
    cudaFuncSetAttribute(gemm_mma<1>, cudaFuncAttributeMaxDynamicSharedMemorySize, GEMM_SMEM);
    cudaFuncSetAttribute(attn_mma, cudaFuncAttributeMaxDynamicSharedMemorySize, ATTN_SMEM);

    // fp32 -> bf16 hi/lo splits (single launch)
    split_all<<<8192, 256>>>(x, W_in, W_out);

    // QKV projection: tiles 64x128 -> grid (3072/128, 4096/64)
    gemm_mma<0><<<dim3(24, 64), 256, GEMM_SMEM>>>(b_in, nullptr);

    // attention
    attn_mma<<<dim3(16, BHH), 128, ATTN_SMEM>>>(attn_bias, attn_mul, kpm);

    // output projection: grid (1024/128, 4096/64)
    gemm_mma<1><<<dim3(8, 64), 256, GEMM_SMEM>>>(b_out, out);
}

// round 17
// speedup vs baseline: 1.8576x; 1.0083x over previous
#include <cuda_runtime.h>
#include <cuda_bf16.h>
#include <cstdint>

// Problem constants
#define SS 1024
#define BB 4
#define HH 16
#define DD 64
#define EE 1024
#define BHH 64   // B*H

// ---------------------------------------------------------------------------
// Scratch (device globals)
// ---------------------------------------------------------------------------
__device__ __nv_bfloat16 g_qhi[BHH * SS * DD], g_qlo[BHH * SS * DD];
__device__ __nv_bfloat16 g_khi[BHH * SS * DD], g_klo[BHH * SS * DD];
__device__ __nv_bfloat16 g_vhi[BHH * SS * DD], g_vlo[BHH * SS * DD];

__device__ __nv_bfloat16 g_xhi[4096 * 1024], g_xlo[4096 * 1024];
__device__ __nv_bfloat16 g_wihi[3072 * 1024], g_wilo[3072 * 1024];
__device__ __nv_bfloat16 g_wohi[1024 * 1024], g_wolo[1024 * 1024];
__device__ __nv_bfloat16 g_ahi[4096 * 1024], g_alo[4096 * 1024];

// ---------------------------------------------------------------------------
// Warp-level MMA helpers (baseline PTX, works on sm_103 non-'a' target)
// ---------------------------------------------------------------------------
__device__ __forceinline__ uint32_t smem_u32(const void* p) {
    uint32_t a;
    asm("{ .reg .u64 t; cvta.to.shared.u64 t, %1; cvt.u32.u64 %0, t; }"
        : "=r"(a) : "l"(p));
    return a;
}

__device__ __forceinline__ void ldm_x4(uint32_t* r, uint32_t addr) {
    asm volatile("ldmatrix.sync.aligned.m8n8.x4.shared.b16 {%0,%1,%2,%3}, [%4];"
                 : "=r"(r[0]), "=r"(r[1]), "=r"(r[2]), "=r"(r[3]) : "r"(addr));
}
__device__ __forceinline__ void ldm_x2(uint32_t* r, uint32_t addr) {
    asm volatile("ldmatrix.sync.aligned.m8n8.x2.shared.b16 {%0,%1}, [%2];"
                 : "=r"(r[0]), "=r"(r[1]) : "r"(addr));
}
__device__ __forceinline__ void ldm_x2t(uint32_t* r, uint32_t addr) {
    asm volatile("ldmatrix.sync.aligned.m8n8.x2.trans.shared.b16 {%0,%1}, [%2];"
                 : "=r"(r[0]), "=r"(r[1]) : "r"(addr));
}

// D(f32) += A(bf16) @ B(bf16), m16n8k16
__device__ __forceinline__ void mma_bf16(float* c, const uint32_t* a, const uint32_t* b) {
    asm volatile(
        "mma.sync.aligned.m16n8k16.row.col.f32.bf16.bf16.f32 "
        "{%0,%1,%2,%3}, {%4,%5,%6,%7}, {%8,%9}, {%0,%1,%2,%3};"
        : "+f"(c[0]), "+f"(c[1]), "+f"(c[2]), "+f"(c[3])
        : "r"(a[0]), "r"(a[1]), "r"(a[2]), "r"(a[3]), "r"(b[0]), "r"(b[1]));
}

// cp.async 16B
__device__ __forceinline__ void cp16(uint32_t dst, const void* src) {
    asm volatile("cp.async.cg.shared.global [%0], [%1], 16;" :: "r"(dst), "l"(src));
}
#define CP_COMMIT() asm volatile("cp.async.commit_group;" ::: "memory")
#define CP_WAIT(N)  asm volatile("cp.async.wait_group %0;" :: "n"(N) : "memory")

// pack two fp32 -> bf16x2 (x0 in low half, x1 in high half)
__device__ __forceinline__ uint32_t pack2(float x0, float x1) {
    uint32_t r;
    asm("cvt.rn.bf16x2.f32 %0, %1, %2;" : "=r"(r) : "f"(x1), "f"(x0));
    return r;
}
// split pair into hi/lo bf16x2
__device__ __forceinline__ void split2(float x0, float x1, uint32_t& hi, uint32_t& lo) {
    uint32_t hv = pack2(x0, x1);
    float h0 = __uint_as_float(hv << 16);
    float h1 = __uint_as_float(hv & 0xFFFF0000u);
    hi = hv;
    lo = pack2(x0 - h0, x1 - h1);
}

// ---------------------------------------------------------------------------
// fp32 -> bf16 hi/lo splits, 4 float4 per thread (MLP=4).
// blocks [0,1024): x | [1024,1792): W_in | [1792,2048): W_out
// ---------------------------------------------------------------------------
__global__ __launch_bounds__(256) void split_all(const float* __restrict__ x,
                                                 const float* __restrict__ wi,
                                                 const float* __restrict__ wo) {
    int bid = blockIdx.x;
    const float* src;
    __nv_bfloat16 *hi, *lo;
    int base;
    if (bid < 1024)      { src = x;  hi = g_xhi;  lo = g_xlo;  base = bid * 1024; }
    else if (bid < 1792) { src = wi; hi = g_wihi; lo = g_wilo; base = (bid - 1024) * 1024; }
    else                 { src = wo; hi = g_wohi; lo = g_wolo; base = (bid - 1792) * 1024; }

    float4 v[4];
#pragma unroll
    for (int t = 0; t < 4; t++)
        v[t] = ((const float4*)src)[base + t * 256 + threadIdx.x];
#pragma unroll
    for (int t = 0; t < 4; t++) {
        int i = base + t * 256 + threadIdx.x;
        uint32_t h0, l0, h1, l1;
        split2(v[t].x, v[t].y, h0, l0);
        split2(v[t].z, v[t].w, h1, l1);
        ((uint2*)hi)[i] = make_uint2(h0, h1);
        ((uint2*)lo)[i] = make_uint2(l0, l1);
    }
}

// ---------------------------------------------------------------------------
// QKV GEMM: CTA tile 64x128, 3 CTAs/SM (round-16 proven body).
// C[m][n] = sum_k x[m][k]*W_in[n][k] + b; scatter bf16 hi/lo q/k/v (q*0.125)
// ---------------------------------------------------------------------------
#define GBUF_U4 1920

__global__ __launch_bounds__(256, 3) void gemm_qkv(const float* __restrict__ bias)
{
    extern __shared__ __align__(16) uint4 smem[];

    const __nv_bfloat16* Ahi = g_xhi;
    const __nv_bfloat16* Alo = g_xlo;
    const __nv_bfloat16* Bhi = g_wihi;
    const __nv_bfloat16* Blo = g_wilo;

    const int tid = threadIdx.x;
    const int lane = tid & 31;
    const int wid = tid >> 5;
    const int wm = wid >> 2;
    const int wn = wid & 3;
    const int bm = blockIdx.y, bn = blockIdx.x;
    const int K = 1024;

    float acc[2][4][4];
#pragma unroll
    for (int mf = 0; mf < 2; mf++)
#pragma unroll
        for (int nf = 0; nf < 4; nf++)
#pragma unroll
            for (int e = 0; e < 4; e++) acc[mf][nf][e] = 0.f;

    const uint32_t uS = smem_u32(smem);
    const __nv_bfloat16* gsrc[4] = {Ahi, Alo, Bhi, Blo};

    auto issue = [&](int kt, int b) {
        const int k0 = kt * 32;
#pragma unroll
        for (int q = 0; q < 6; q++) {
            int c = q * 256 + tid;
            int a, d;
            if (c < 256)       { a = 0; d = c; }
            else if (c < 512)  { a = 1; d = c - 256; }
            else if (c < 1024) { a = 2; d = c - 512; }
            else               { a = 3; d = c - 1024; }
            int row = d >> 2, kc = d & 3;
            int gr = (a < 2) ? (bm * 64 + row) : (bn * 128 + row);
            int arrOff = (a == 0) ? 0 : (a == 1) ? 320 : (a == 2) ? 640 : 1280;
            const __nv_bfloat16* src = gsrc[a] + (size_t)gr * K + k0 + kc * 8;
            uint32_t dst = uS + (uint32_t)(b * GBUF_U4 + arrOff + row * 5 + kc) * 16u;
            cp16(dst, src);
        }
        CP_COMMIT();
    };

    const int a_row = wm * 32 + (lane & 7) + ((lane >> 3) & 1) * 8;
    const int a_kc  = (lane >> 4) & 1;
    const int b_row = wn * 32 + (lane & 7);
    const int b_kc  = (lane >> 3) & 1;

    issue(0, 0);

    for (int kt = 0; kt < 32; kt++) {
        const int b = kt & 1;
        CP_WAIT(0);
        __syncthreads();
        if (kt < 31) issue(kt + 1, b ^ 1);

        const uint32_t uAhi = uS + (uint32_t)(b * GBUF_U4) * 16u;
        const uint32_t uAlo = uAhi + 320u * 16u;
        const uint32_t uBhi = uAhi + 640u * 16u;
        const uint32_t uBlo = uAhi + 1280u * 16u;

#pragma unroll
        for (int ks = 0; ks < 2; ks++) {
            uint32_t ah[2][4], al[2][4], bh[4][2], bl[4][2];
#pragma unroll
            for (int mf = 0; mf < 2; mf++) {
                uint32_t off = (uint32_t)(((a_row + mf * 16) * 5 + ks * 2 + a_kc) * 16);
                ldm_x4(ah[mf], uAhi + off);
                ldm_x4(al[mf], uAlo + off);
            }
#pragma unroll
            for (int nf = 0; nf < 4; nf++) {
                uint32_t off = (uint32_t)(((b_row + nf * 8) * 5 + ks * 2 + b_kc) * 16);
                ldm_x2(bh[nf], uBhi + off);
                ldm_x2(bl[nf], uBlo + off);
            }
#pragma unroll
            for (int mf = 0; mf < 2; mf++)
#pragma unroll
                for (int nf = 0; nf < 4; nf++) {
                    mma_bf16(acc[mf][nf], ah[mf], bh[nf]);
                    mma_bf16(acc[mf][nf], ah[mf], bl[nf]);
                    mma_bf16(acc[mf][nf], al[mf], bh[nf]);
                }
        }
    }

#pragma unroll
    for (int mf = 0; mf < 2; mf++) {
#pragma unroll
        for (int nf = 0; nf < 4; nf++) {
#pragma unroll
            for (int e = 0; e < 4; e++) {
                int m = bm * 64 + wm * 32 + mf * 16 + (lane >> 2) + ((e >> 1) & 1) * 8;
                int n = bn * 128 + wn * 32 + nf * 8 + (lane & 3) * 2 + (e & 1);
                float v = acc[mf][nf][e] + bias[n];
                int sidx = m >> 2;
                int bt = m & 3;
                int h = n / 192;
                int rr = n - h * 192;
                int bh2 = bt * HH + h;
                __nv_bfloat16 *dh, *dl;
                int dcol;
                if (rr < 64)       { dh = g_qhi; dl = g_qlo; dcol = rr;       v *= 0.125f; }
                else if (rr < 128) { dh = g_khi; dl = g_klo; dcol = rr - 64;  }
                else               { dh = g_vhi; dl = g_vlo; dcol = rr - 128; }
                size_t idx = ((size_t)bh2 * SS + sidx) * DD + dcol;
                __nv_bfloat16 hv = __float2bfloat16(v);
                __nv_bfloat16 lv = __float2bfloat16(v - __bfloat162float(hv));
                dh[idx] = hv;
                dl[idx] = lv;
            }
        }
    }
}

// ---------------------------------------------------------------------------
// Output GEMM: CTA tile 128x128, 2 CTAs/SM, grid 256 -> SINGLE WAVE
// (round-15 proven body).
// ---------------------------------------------------------------------------
#define BUF_U4 2560
#define ARR_U4 640

__global__ __launch_bounds__(256) void gemm_out(
    const float* __restrict__ bias, float* __restrict__ Cout)
{
    extern __shared__ __align__(16) uint4 smem[];

    const __nv_bfloat16* Ahi = g_ahi;
    const __nv_bfloat16* Alo = g_alo;
    const __nv_bfloat16* Bhi = g_wohi;
    const __nv_bfloat16* Blo = g_wolo;

    const int tid = threadIdx.x;
    const int lane = tid & 31;
    const int wid = tid >> 5;
    const int wm = wid >> 2;
    const int wn = wid & 3;
    const int bm = blockIdx.y, bn = blockIdx.x;
    const int K = 1024;

    float acc[4][4][4];
#pragma unroll
    for (int mf = 0; mf < 4; mf++)
#pragma unroll
        for (int nf = 0; nf < 4; nf++)
#pragma unroll
            for (int e = 0; e < 4; e++) acc[mf][nf][e] = 0.f;

    const uint32_t uS = smem_u32(smem);
    const __nv_bfloat16* gsrc[4] = {Ahi, Alo, Bhi, Blo};

    auto issue = [&](int kt, int b) {
        const int k0 = kt * 32;
#pragma unroll
        for (int q = 0; q < 8; q++) {
            int a = q >> 1;
            int sub = (q & 1) * 256 + tid;
            int row = sub >> 2, kc = sub & 3;
            int gr = (a < 2 ? bm : bn) * 128 + row;
            const __nv_bfloat16* src = gsrc[a] + (size_t)gr * K + k0 + kc * 8;
            uint32_t dst = uS + (uint32_t)(b * BUF_U4 + a * ARR_U4 + row * 5 + kc) * 16u;
            cp16(dst, src);
        }
        CP_COMMIT();
    };

    const int a_row = wm * 64 + (lane & 7) + ((lane >> 3) & 1) * 8;
    const int a_kc  = (lane >> 4) & 1;
    const int b_row = wn * 32 + (lane & 7);
    const int b_kc  = (lane >> 3) & 1;

    issue(0, 0);

    for (int kt = 0; kt < 32; kt++) {
        const int b = kt & 1;
        CP_WAIT(0);
        __syncthreads();
        if (kt < 31) issue(kt + 1, b ^ 1);

        const uint32_t uAhi = uS + (uint32_t)(b * BUF_U4) * 16u;
        const uint32_t uAlo = uAhi + ARR_U4 * 16u;
        const uint32_t uBhi = uAlo + ARR_U4 * 16u;
        const uint32_t uBlo = uBhi + ARR_U4 * 16u;

#pragma unroll
        for (int ks = 0; ks < 2; ks++) {
            uint32_t ah[4][4], al[4][4], bh[4][2], bl[4][2];
#pragma unroll
            for (int mf = 0; mf < 4; mf++) {
                uint32_t off = (uint32_t)(((a_row + mf * 16) * 5 + ks * 2 + a_kc) * 16);
                ldm_x4(ah[mf], uAhi + off);
                ldm_x4(al[mf], uAlo + off);
            }
#pragma unroll
            for (int nf = 0; nf < 4; nf++) {
                uint32_t off = (uint32_t)(((b_row + nf * 8) * 5 + ks * 2 + b_kc) * 16);
                ldm_x2(bh[nf], uBhi + off);
                ldm_x2(bl[nf], uBlo + off);
            }
#pragma unroll
            for (int mf = 0; mf < 4; mf++)
#pragma unroll
                for (int nf = 0; nf < 4; nf++) {
                    mma_bf16(acc[mf][nf], ah[mf], bh[nf]);
                    mma_bf16(acc[mf][nf], ah[mf], bl[nf]);
                    mma_bf16(acc[mf][nf], al[mf], bh[nf]);
                }
        }
        __syncthreads();
    }

#pragma unroll
    for (int mf = 0; mf < 4; mf++) {
#pragma unroll
        for (int nf = 0; nf < 4; nf++) {
#pragma unroll
            for (int e = 0; e < 4; e++) {
                int m = bm * 128 + wm * 64 + mf * 16 + (lane >> 2) + ((e >> 1) & 1) * 8;
                int n = bn * 128 + wn * 32 + nf * 8 + (lane & 3) * 2 + (e & 1);
                Cout[(size_t)m * 1024 + n] = acc[mf][nf][e] + bias[n];
            }
        }
    }
}

// ---------------------------------------------------------------------------
// Flash attention on mma.sync with REGISTER-PREFETCHED bias/mul stream.
// Per staging thread the column group is constant across rows
// ((tid + t*128) & 15 == tid & 15), so next tile's 8x2 float4 + 1 mask int4
// fit in regs and are fetched during the previous tile's compute.
// ---------------------------------------------------------------------------
#define TSWZ(row, ch) ((((row)) << 7) + ((((ch) ^ ((row) & 7))) << 4))
#define SBP 68

__global__ __launch_bounds__(128) void attn_mma(
    const float* __restrict__ bias_g, const float* __restrict__ mul_g,
    const int* __restrict__ kpm)
{
    extern __shared__ uint8_t sm[];
    float* sB = (float*)(sm + 32768);
    float* sM = (float*)(sm + 50176);

    const int tid = threadIdx.x;
    const int lane = tid & 31;
    const int warp = tid >> 5;
    const int qt = blockIdx.x, bh = blockIdx.y;
    const int b = bh >> 4, h = bh & 15;
    const uint32_t uSm = smem_u32(sm);

    const __nv_bfloat16* qhi = g_qhi + ((size_t)bh * SS + qt * 64) * DD;
    const __nv_bfloat16* qlo = g_qlo + ((size_t)bh * SS + qt * 64) * DD;
    const __nv_bfloat16* khi = g_khi + (size_t)bh * SS * DD;
    const __nv_bfloat16* klo = g_klo + (size_t)bh * SS * DD;
    const __nv_bfloat16* vhi = g_vhi + (size_t)bh * SS * DD;
    const __nv_bfloat16* vlo = g_vlo + (size_t)bh * SS * DD;
    const float* bbase = bias_g + ((size_t)bh * SS + qt * 64) * SS;
    const float* mbase = mul_g + ((size_t)bh * SS + qt * 64) * SS;
    const int* kp = kpm + b * SS;

    // staging geometry (constant per thread)
    const int st_col = (tid & 15) * 4;
    const int st_row0 = tid >> 4;          // + t*8

    // prefetch registers for the bias/mul/mask stream
    float4 pbv[8], pmv[8];
    int4 pmk;

    auto prefetch = [&](int kt2) {
        int k0n = kt2 * 64;
        pmk = *(const int4*)(kp + k0n + st_col);
#pragma unroll
        for (int t = 0; t < 8; t++) {
            int row = st_row0 + t * 8;
            pbv[t] = *(const float4*)(bbase + (size_t)row * SS + k0n + st_col);
            pmv[t] = *(const float4*)(mbase + (size_t)row * SS + k0n + st_col);
        }
    };

    prefetch(0);   // in flight during Q staging

    // ---- stage Q into smem (at sB region), load A-fragments, then free it
#pragma unroll
    for (int t = 0; t < 4; t++) {
        int idx = tid + t * 128;
        int row = idx >> 3, ch = idx & 7;
        *(uint4*)(sm + 32768 + TSWZ(row, ch)) = *(const uint4*)(qhi + row * 64 + ch * 8);
        *(uint4*)(sm + 40960 + TSWZ(row, ch)) = *(const uint4*)(qlo + row * 64 + ch * 8);
    }
    __syncthreads();

    uint32_t qh[4][4], ql[4][4];
    {
        int arow = warp * 16 + (lane & 7) + ((lane >> 3) & 1) * 8;
        int akc = (lane >> 4) & 1;
#pragma unroll
        for (int ds = 0; ds < 4; ds++) {
            uint32_t off = (uint32_t)TSWZ(arow, ds * 2 + akc);
            ldm_x4(qh[ds], uSm + 32768 + off);
            ldm_x4(ql[ds], uSm + 40960 + off);
        }
    }

    float acc[8][4];
#pragma unroll
    for (int i = 0; i < 8; i++)
#pragma unroll
        for (int e = 0; e < 4; e++) acc[i][e] = 0.f;
    float m0 = 0.f, m1 = 0.f, l0 = 1.f, l1 = 1.f;   // phantom logit 0

    const int r0 = warp * 16 + (lane >> 2);
    const int cc = (lane & 3) * 2;
    const int brow = lane & 7;
    const int bkc = (lane >> 3) & 1;
    const int vrow = (lane & 7) + ((lane >> 3) & 1) * 8;

    for (int kt = 0; kt < 16; kt++) {
        const int k0 = kt * 64;
        __syncthreads();   // all warps done with previous tile's smem

        // K/V hi/lo via cp.async (L2-resident; overlaps the staging below)
#pragma unroll
        for (int t = 0; t < 4; t++) {
            int idx = tid + t * 128;
            int row = idx >> 3, ch = idx & 7;
            size_t go = (size_t)(k0 + row) * 64 + ch * 8;
            uint32_t so = TSWZ(row, ch);
            cp16(uSm + so,         khi + go);
            cp16(uSm + 8192 + so,  klo + go);
            cp16(uSm + 16384 + so, vhi + go);
            cp16(uSm + 24576 + so, vlo + go);
        }
        CP_COMMIT();

        // stage bias/mul from prefetch regs, mask folded in (pure reg->smem)
#pragma unroll
        for (int t = 0; t < 8; t++) {
            int row = st_row0 + t * 8;
            float4 bv = pbv[t], mv = pmv[t];
            if (pmk.x) { bv.x = -1e30f; mv.x = 0.f; }
            if (pmk.y) { bv.y = -1e30f; mv.y = 0.f; }
            if (pmk.z) { bv.z = -1e30f; mv.z = 0.f; }
            if (pmk.w) { bv.w = -1e30f; mv.w = 0.f; }
            *(float4*)&sB[row * SBP + st_col] = bv;
            *(float4*)&sM[row * SBP + st_col] = mv;
        }
        if (kt < 15) prefetch(kt + 1);   // DRAM latency hidden behind compute
        CP_WAIT(0);
        __syncthreads();

        // ---- S = bias + Q K^T (3-term)
        float s[8][4];
#pragma unroll
        for (int nf = 0; nf < 8; nf++) {
            float2 t0 = *(float2*)&sB[r0 * SBP + nf * 8 + cc];
            float2 t1 = *(float2*)&sB[(r0 + 8) * SBP + nf * 8 + cc];
            s[nf][0] = t0.x; s[nf][1] = t0.y; s[nf][2] = t1.x; s[nf][3] = t1.y;
        }
#pragma unroll
        for (int ds = 0; ds < 4; ds++) {
#pragma unroll
            for (int nf = 0; nf < 8; nf++) {
                uint32_t kh2[2], kl2[2];
                uint32_t off = (uint32_t)TSWZ(nf * 8 + brow, ds * 2 + bkc);
                ldm_x2(kh2, uSm + off);
                ldm_x2(kl2, uSm + 8192 + off);
                mma_bf16(s[nf], qh[ds], kh2);
                mma_bf16(s[nf], qh[ds], kl2);
                mma_bf16(s[nf], ql[ds], kh2);
            }
        }

        // ---- online softmax_1
        float tm0 = s[0][0], tm1 = s[0][2];
#pragma unroll
        for (int nf = 0; nf < 8; nf++) {
            tm0 = fmaxf(tm0, fmaxf(s[nf][0], s[nf][1]));
            tm1 = fmaxf(tm1, fmaxf(s[nf][2], s[nf][3]));
        }
        tm0 = fmaxf(tm0, __shfl_xor_sync(0xffffffffu, tm0, 1));
        tm0 = fmaxf(tm0, __shfl_xor_sync(0xffffffffu, tm0, 2));
        tm1 = fmaxf(tm1, __shfl_xor_sync(0xffffffffu, tm1, 1));
        tm1 = fmaxf(tm1, __shfl_xor_sync(0xffffffffu, tm1, 2));
        float mn0 = fmaxf(m0, tm0), mn1 = fmaxf(m1, tm1);
        float sc0 = __expf(m0 - mn0), sc1 = __expf(m1 - mn1);
        m0 = mn0; m1 = mn1;
        float rs0 = 0.f, rs1 = 0.f;
#pragma unroll
        for (int nf = 0; nf < 8; nf++) {
            s[nf][0] = __expf(s[nf][0] - mn0);
            s[nf][1] = __expf(s[nf][1] - mn0);
            s[nf][2] = __expf(s[nf][2] - mn1);
            s[nf][3] = __expf(s[nf][3] - mn1);
            rs0 += s[nf][0] + s[nf][1];
            rs1 += s[nf][2] + s[nf][3];
        }
        rs0 += __shfl_xor_sync(0xffffffffu, rs0, 1);
        rs0 += __shfl_xor_sync(0xffffffffu, rs0, 2);
        rs1 += __shfl_xor_sync(0xffffffffu, rs1, 1);
        rs1 += __shfl_xor_sync(0xffffffffu, rs1, 2);
        l0 = l0 * sc0 + rs0;
        l1 = l1 * sc1 + rs1;
#pragma unroll
        for (int i = 0; i < 8; i++) {
            acc[i][0] *= sc0; acc[i][1] *= sc0;
            acc[i][2] *= sc1; acc[i][3] *= sc1;
        }

        // ---- p *= abm
#pragma unroll
        for (int nf = 0; nf < 8; nf++) {
            float2 t0 = *(float2*)&sM[r0 * SBP + nf * 8 + cc];
            float2 t1 = *(float2*)&sM[(r0 + 8) * SBP + nf * 8 + cc];
            s[nf][0] *= t0.x; s[nf][1] *= t0.y; s[nf][2] *= t1.x; s[nf][3] *= t1.y;
        }

        // ---- acc += P V (3-term)
#pragma unroll
        for (int ks = 0; ks < 4; ks++) {
            uint32_t ahi[4], alo[4];
            split2(s[2 * ks][0],     s[2 * ks][1],     ahi[0], alo[0]);
            split2(s[2 * ks][2],     s[2 * ks][3],     ahi[1], alo[1]);
            split2(s[2 * ks + 1][0], s[2 * ks + 1][1], ahi[2], alo[2]);
            split2(s[2 * ks + 1][2], s[2 * ks + 1][3], ahi[3], alo[3]);
#pragma unroll
            for (int nfd = 0; nfd < 8; nfd++) {
                uint32_t vh2[2], vl2[2];
                uint32_t off = (uint32_t)TSWZ(ks * 16 + vrow, nfd);
                ldm_x2t(vh2, uSm + 16384 + off);
                ldm_x2t(vl2, uSm + 24576 + off);
                mma_bf16(acc[nfd], ahi, vh2);
                mma_bf16(acc[nfd], ahi, vl2);
                mma_bf16(acc[nfd], alo, vh2);
            }
        }
    }

    // ---- epilogue
    float inv0 = 1.0f / l0, inv1 = 1.0f / l1;
    int q0 = qt * 64 + r0;
    size_t o0 = ((size_t)q0 * BB + b) * EE + h * 64;
    size_t o1 = ((size_t)(q0 + 8) * BB + b) * EE + h * 64;
#pragma unroll
    for (int nfd = 0; nfd < 8; nfd++) {
        int dc = nfd * 8 + cc;
        uint32_t h0, lo0, h1, lo1;
        split2(acc[nfd][0] * inv0, acc[nfd][1] * inv0, h0, lo0);
        split2(acc[nfd][2] * inv1, acc[nfd][3] * inv1, h1, lo1);
        *(uint32_t*)(g_ahi + o0 + dc) = h0;
        *(uint32_t*)(g_alo + o0 + dc) = lo0;
        *(uint32_t*)(g_ahi + o1 + dc) = h1;
        *(uint32_t*)(g_alo + o1 + dc) = lo1;
    }
}

// ---------------------------------------------------------------------------
extern "C" void kernel_launch(void* const* d_in, const int* in_sizes, int n_in,
                              void* d_out, int out_size)
{
    (void)in_sizes; (void)n_in; (void)out_size;
    const float* x         = (const float*)d_in[0];
    const float* attn_bias = (const float*)d_in[1];
    const float* attn_mul  = (const float*)d_in[2];
    const int*   kpm       = (const int*)d_in[3];
    const float* W_in      = (const float*)d_in[4];
    const float* b_in      = (const float*)d_in[5];
    const float* W_out     = (const float*)d_in[6];
    const float* b_out     = (const float*)d_in[7];
    float* out = (float*)d_out;

    const int QKV_SMEM  = 2 * GBUF_U4 * 16;   // 61440
    const int OUT_SMEM  = 2 * BUF_U4 * 16;    // 81920
    const int ATTN_SMEM = 67584;
    cudaFuncSetAttribute(gemm_qkv, cudaFuncAttributeMaxDynamicSharedMemorySize, QKV_SMEM);
    cudaFuncSetAttribute(gemm_out, cudaFuncAttributeMaxDynamicSharedMemorySize, OUT_SMEM);
    cudaFuncSetAttribute(attn_mma, cudaFuncAttributeMaxDynamicSharedMemorySize, ATTN_SMEM);

    // fp32 -> bf16 hi/lo splits (MLP=4)
    split_all<<<2048, 256>>>(x, W_in, W_out);

    // QKV projection: 64x128 tiles, grid (3072/128, 4096/64)
    gemm_qkv<<<dim3(24, 64), 256, QKV_SMEM>>>(b_in);

    // attention
    attn_mma<<<dim3(16, BHH), 128, ATTN_SMEM>>>(attn_bias, attn_mul, kpm);

    // output projection: 128x128 tiles, grid (1024/128, 4096/128) -> 256 CTAs
    gemm_out<<<dim3(8, 32), 256, OUT_SMEM>>>(b_out, out);
}